// round 3
// baseline (speedup 1.0000x reference)
#include <cuda_runtime.h>
#include <math.h>

#define BLC 4
#define LEN 1024
#define HN 16
#define DH 64
#define EMB 1024
#define BL (BLC*LEN)          // 4096 rows total
#define MINV (-1.7014117e38f) // float32 min / 2

// Scratch (allocation-free rule: __device__ globals)
__device__ float g_Q[BL*EMB];
__device__ float g_K[BL*EMB];
__device__ float g_V[BL*EMB];
__device__ float g_KT[BL*EMB];     // [b*16+h][64 d][1024 pos]
__device__ float g_WoT[EMB*EMB];   // Wo transposed: [k][n]
__device__ float g_Val[BL*EMB];
__device__ float g_Y[BL*EMB];
__device__ float g_rowM[64*LEN];   // per (bh,row) softmax max
__device__ float g_rowL[64*LEN];   // per (bh,row) softmax denom

// ---------------------------------------------------------------------------
// tf32 helpers
// ---------------------------------------------------------------------------
__device__ __forceinline__ unsigned f2tf(float f) {
    unsigned u; asm("cvt.rna.tf32.f32 %0, %1;" : "=r"(u) : "f"(f)); return u;
}
__device__ __forceinline__ uint4 cvt4(float4 v) {
    uint4 u; u.x = f2tf(v.x); u.y = f2tf(v.y); u.z = f2tf(v.z); u.w = f2tf(v.w); return u;
}
__device__ __forceinline__ void mma8(float* c,
                                     unsigned a0, unsigned a1, unsigned a2, unsigned a3,
                                     unsigned b0, unsigned b1) {
    asm volatile(
        "mma.sync.aligned.m16n8k8.row.col.f32.tf32.tf32.f32 "
        "{%0,%1,%2,%3}, {%4,%5,%6,%7}, {%8,%9}, {%0,%1,%2,%3};"
        : "+f"(c[0]), "+f"(c[1]), "+f"(c[2]), "+f"(c[3])
        : "r"(a0), "r"(a1), "r"(a2), "r"(a3), "r"(b0), "r"(b1));
}

// ---------------------------------------------------------------------------
// Kernel 1: QKV projections via tf32 mma (unchanged from round 2)
// ---------------------------------------------------------------------------
#define AS_STRIDE 36
#define BS_STRIDE 72

__global__ __launch_bounds__(256) void qkv_mma(
    const float* __restrict__ x,
    const float* __restrict__ Wq, const float* __restrict__ bq,
    const float* __restrict__ Wk, const float* __restrict__ bk,
    const float* __restrict__ Wv, const float* __restrict__ bv)
{
    const float* W; const float* bias; float* out;
    int z = blockIdx.z;
    if (z == 0)      { W = Wq; bias = bq; out = g_Q; }
    else if (z == 1) { W = Wk; bias = bk; out = g_K; }
    else             { W = Wv; bias = bv; out = g_V; }

    __shared__ unsigned As[128 * AS_STRIDE];
    __shared__ unsigned Bs[32 * BS_STRIDE];

    int tid = threadIdx.x;
    int wid = tid >> 5, lane = tid & 31;
    int wm = wid & 3, wn = wid >> 2;
    unsigned g = lane >> 2, t = lane & 3;

    int rowbase = blockIdx.y * 128;
    int head    = blockIdx.x;

    float acc[2][4][4] = {};

    for (int kb = 0; kb < EMB; kb += 32) {
        #pragma unroll
        for (int e = 0; e < 4; e++) {
            int r  = (tid >> 3) + 32 * e;
            int c4 = (tid & 7) * 4;
            float4 v = *(const float4*)&x[(size_t)(rowbase + r) * EMB + kb + c4];
            *(uint4*)&As[r * AS_STRIDE + c4] = cvt4(v);
        }
        #pragma unroll
        for (int e = 0; e < 2; e++) {
            int k  = (tid >> 4) + 16 * e;
            int c4 = (tid & 15) * 4;
            float4 v = *(const float4*)&W[(size_t)head * (EMB * DH) + (size_t)(kb + k) * DH + c4];
            *(uint4*)&Bs[k * BS_STRIDE + c4] = cvt4(v);
        }
        __syncthreads();

        #pragma unroll
        for (int ks = 0; ks < 4; ks++) {
            int k0 = ks * 8;
            unsigned a[2][4];
            #pragma unroll
            for (int mi = 0; mi < 2; mi++) {
                int base = (wm * 32 + mi * 16 + g) * AS_STRIDE + k0 + t;
                a[mi][0] = As[base];
                a[mi][1] = As[base + 8 * AS_STRIDE];
                a[mi][2] = As[base + 4];
                a[mi][3] = As[base + 8 * AS_STRIDE + 4];
            }
            unsigned b[4][2];
            #pragma unroll
            for (int ni = 0; ni < 4; ni++) {
                int cb = wn * 32 + ni * 8 + g;
                b[ni][0] = Bs[(k0 + t) * BS_STRIDE + cb];
                b[ni][1] = Bs[(k0 + t + 4) * BS_STRIDE + cb];
            }
            #pragma unroll
            for (int mi = 0; mi < 2; mi++)
                #pragma unroll
                for (int ni = 0; ni < 4; ni++)
                    mma8(acc[mi][ni], a[mi][0], a[mi][1], a[mi][2], a[mi][3],
                         b[ni][0], b[ni][1]);
        }
        __syncthreads();
    }

    #pragma unroll
    for (int mi = 0; mi < 2; mi++) {
        int row = rowbase + wm * 32 + mi * 16 + g;
        #pragma unroll
        for (int ni = 0; ni < 4; ni++) {
            int col = head * 64 + wn * 32 + ni * 8 + 2 * t;
            float b0 = bias[col], b1 = bias[col + 1];
            float2 v0 = make_float2(acc[mi][ni][0] + b0, acc[mi][ni][1] + b1);
            float2 v1 = make_float2(acc[mi][ni][2] + b0, acc[mi][ni][3] + b1);
            *(float2*)&out[(size_t)row * EMB + col]       = v0;
            *(float2*)&out[(size_t)(row + 8) * EMB + col] = v1;
        }
    }
}

// ---------------------------------------------------------------------------
// Transposes (unchanged)
// ---------------------------------------------------------------------------
__global__ void transpose_k() {
    __shared__ float tl[32][33];
    int bh = blockIdx.z;
    int b = bh >> 4, h = bh & 15;
    int p0 = blockIdx.x * 32, d0 = blockIdx.y * 32;
    int tx = threadIdx.x, ty = threadIdx.y;
    #pragma unroll
    for (int j = 0; j < 4; j++)
        tl[ty + 8 * j][tx] =
            g_K[(size_t)(b * LEN + p0 + ty + 8 * j) * EMB + h * DH + d0 + tx];
    __syncthreads();
    #pragma unroll
    for (int j = 0; j < 4; j++)
        g_KT[((size_t)bh * DH + d0 + ty + 8 * j) * LEN + p0 + tx] = tl[tx][ty + 8 * j];
}

__global__ void transpose_wo(const float* __restrict__ Wo) {
    __shared__ float tl[32][33];
    int n0 = blockIdx.y * 32, k0 = blockIdx.x * 32;
    int tx = threadIdx.x, ty = threadIdx.y;
    #pragma unroll
    for (int j = 0; j < 4; j++)
        tl[ty + 8 * j][tx] = Wo[(size_t)(n0 + ty + 8 * j) * EMB + k0 + tx];
    __syncthreads();
    #pragma unroll
    for (int j = 0; j < 4; j++)
        g_WoT[(size_t)(k0 + ty + 8 * j) * EMB + n0 + tx] = tl[tx][ty + 8 * j];
}

// ---------------------------------------------------------------------------
// Kernel 2a: score_kernel — S = masked(QK^T*scale) chunk-streamed to gmem
// (the atten region of d_out), with online row max/sum. 32 q-rows per block.
// smem ~65 KB -> 3 CTAs/SM.
// ---------------------------------------------------------------------------
#define SQS  68    // Q tile stride (tf32)
#define SKTS 136   // K^T chunk stride
#define SSTR 132   // S chunk stride (== 4 mod 32)
#define SVS  72    // V chunk stride

__global__ __launch_bounds__(256) void score_kernel(
    const int* __restrict__ mask, float* __restrict__ Sout)
{
    extern __shared__ float sm[];
    float* sQ  = sm;                 // 32*68   = 2176
    float* sKT = sQ + 32 * SQS;      // 64*136  = 8704
    float* sS  = sKT + 64 * SKTS;    // 32*132  = 4224
    float* sMk = sS + 32 * SSTR;     // 1024
    float* sM  = sMk + 1024;         // 32
    float* sL  = sM + 32;            // 32

    int tile = blockIdx.x, bh = blockIdx.y;
    int b = bh >> 4, h = bh & 15;
    int l0 = tile * 32;
    int tid = threadIdx.x;
    int wid = tid >> 5, lane = tid & 31;
    unsigned g = lane >> 2, t = lane & 3;

    // Stage Q tile [32 x 64] (tf32)
    #pragma unroll
    for (int e = 0; e < 2; e++) {
        int r  = (tid >> 4) + 16 * e;
        int d4 = (tid & 15) * 4;
        float4 v = *(const float4*)&g_Q[(size_t)(b * LEN + l0 + r) * EMB + h * DH + d4];
        uint4 u = cvt4(v);
        *(uint4*)&sQ[r * SQS + d4] = u;
    }
    #pragma unroll
    for (int e = 0; e < 4; e++) {
        int c = tid + 256 * e;
        sMk[c] = (float)mask[b * LEN + c];
    }
    if (tid < 32) { sM[tid] = -3.4e38f; sL[tid] = 0.0f; }
    __syncthreads();

    const unsigned* uQ  = (const unsigned*)sQ;
    const unsigned* uKT = (const unsigned*)sKT;
    const float scale = 0.125f;

    for (int kt = 0; kt < 8; kt++) {
        int p0 = kt * 128;
        // Stage K^T chunk [64 d][128 pos]
        #pragma unroll
        for (int e = 0; e < 8; e++) {
            int d  = (tid >> 5) + 8 * e;
            int p4 = (tid & 31) * 4;
            float4 v = *(const float4*)&g_KT[((size_t)bh * DH + d) * LEN + p0 + p4];
            *(uint4*)&sKT[d * SKTS + p4] = cvt4(v);
        }
        __syncthreads();

        float c[2][2][4] = {};
        #pragma unroll
        for (int ks = 0; ks < 8; ks++) {
            int k0 = ks * 8;
            unsigned a[2][4];
            #pragma unroll
            for (int mi = 0; mi < 2; mi++) {
                int base = (mi * 16 + g) * SQS + k0 + t;
                a[mi][0] = uQ[base];
                a[mi][1] = uQ[base + 8 * SQS];
                a[mi][2] = uQ[base + 4];
                a[mi][3] = uQ[base + 8 * SQS + 4];
            }
            #pragma unroll
            for (int ni = 0; ni < 2; ni++) {
                int cb = wid * 16 + ni * 8 + g;
                unsigned b0 = uKT[(k0 + t) * SKTS + cb];
                unsigned b1 = uKT[(k0 + t + 4) * SKTS + cb];
                mma8(c[0][ni], a[0][0], a[0][1], a[0][2], a[0][3], b0, b1);
                mma8(c[1][ni], a[1][0], a[1][1], a[1][2], a[1][3], b0, b1);
            }
        }
        // Store masked+scaled chunk into sS (local cols)
        #pragma unroll
        for (int mi = 0; mi < 2; mi++) {
            int r0 = mi * 16 + g;
            #pragma unroll
            for (int ni = 0; ni < 2; ni++) {
                int colL = wid * 16 + ni * 8 + 2 * t;
                float m0 = sMk[p0 + colL], m1 = sMk[p0 + colL + 1];
                float2 v0 = make_float2((m0 != 0.0f) ? c[mi][ni][0] * scale : MINV,
                                        (m1 != 0.0f) ? c[mi][ni][1] * scale : MINV);
                float2 v1 = make_float2((m0 != 0.0f) ? c[mi][ni][2] * scale : MINV,
                                        (m1 != 0.0f) ? c[mi][ni][3] * scale : MINV);
                *(float2*)&sS[r0 * SSTR + colL]       = v0;
                *(float2*)&sS[(r0 + 8) * SSTR + colL] = v1;
            }
        }
        __syncthreads();

        // Write raw S chunk to gmem (atten region)
        {
            int r  = tid >> 3;
            int c0 = (tid & 7) * 16;
            float* dst = Sout + ((size_t)(b * HN + h) * LEN + (l0 + r)) * LEN + p0 + c0;
            #pragma unroll
            for (int i = 0; i < 4; i++)
                *(float4*)&dst[4 * i] = *(float4*)&sS[r * SSTR + c0 + 4 * i];
        }
        // Online row max/sum update: warp wid owns rows [wid*4, wid*4+4)
        {
            int r   = wid * 4 + (lane >> 3);
            int c0  = (lane & 7) * 16;
            const float* row = sS + r * SSTR + c0;
            float mx = -3.4e38f;
            #pragma unroll
            for (int i = 0; i < 16; i++) mx = fmaxf(mx, row[i]);
            mx = fmaxf(mx, __shfl_xor_sync(0xffffffffu, mx, 1));
            mx = fmaxf(mx, __shfl_xor_sync(0xffffffffu, mx, 2));
            mx = fmaxf(mx, __shfl_xor_sync(0xffffffffu, mx, 4));
            float m_old = sM[r];
            float m_tot = fmaxf(m_old, mx);
            float s = 0.0f;
            #pragma unroll
            for (int i = 0; i < 16; i++) s += __expf(row[i] - m_tot);
            s += __shfl_xor_sync(0xffffffffu, s, 1);
            s += __shfl_xor_sync(0xffffffffu, s, 2);
            s += __shfl_xor_sync(0xffffffffu, s, 4);
            if ((lane & 7) == 0) {
                sL[r] = sL[r] * __expf(m_old - m_tot) + s;
                sM[r] = m_tot;
            }
        }
        __syncthreads();
    }

    if (tid < 32) {
        g_rowM[bh * LEN + l0 + tid] = sM[tid];
        g_rowL[bh * LEN + l0 + tid] = sL[tid];
    }
}

// ---------------------------------------------------------------------------
// Kernel 2b: pv_kernel — read raw S from atten region, finalize softmax
// (overwrite atten with probs), and compute P @ V -> g_Val.
// smem ~54 KB -> 4 CTAs/SM.
// ---------------------------------------------------------------------------
__global__ __launch_bounds__(256) void pv_kernel(float* __restrict__ atten)
{
    extern __shared__ float sm[];
    float* sP = sm;                  // 32*132 = 4224 (tf32 bits)
    float* sV = sP + 32 * SSTR;      // 128*72 = 9216
    float* sM = sV + 128 * SVS;      // 32
    float* sLi = sM + 32;            // 32

    int tile = blockIdx.x, bh = blockIdx.y;
    int b = bh >> 4, h = bh & 15;
    int l0 = tile * 32;
    int tid = threadIdx.x;
    int wid = tid >> 5, lane = tid & 31;
    unsigned g = lane >> 2, t = lane & 3;

    if (tid < 32) {
        sM[tid]  = g_rowM[bh * LEN + l0 + tid];
        sLi[tid] = 1.0f / g_rowL[bh * LEN + l0 + tid];
    }
    __syncthreads();

    const unsigned* uP = (const unsigned*)sP;
    const unsigned* uV = (const unsigned*)sV;

    float cv[2][4] = {};

    for (int mt = 0; mt < 8; mt++) {
        int p0 = mt * 128;
        // Load raw S chunk, finalize to probs, write atten back, stage tf32 P
        {
            int r  = tid >> 3;
            int c0 = (tid & 7) * 16;
            float m = sM[r], li = sLi[r];
            float* grow = atten + ((size_t)(b * HN + h) * LEN + (l0 + r)) * LEN + p0 + c0;
            #pragma unroll
            for (int i = 0; i < 4; i++) {
                float4 v = *(float4*)&grow[4 * i];
                v.x = __expf(v.x - m) * li;
                v.y = __expf(v.y - m) * li;
                v.z = __expf(v.z - m) * li;
                v.w = __expf(v.w - m) * li;
                *(float4*)&grow[4 * i] = v;
                *(uint4*)&sP[r * SSTR + c0 + 4 * i] = cvt4(v);
            }
        }
        // Stage V chunk [128 pos][64 d]
        #pragma unroll
        for (int e = 0; e < 8; e++) {
            int p  = (tid >> 4) + 16 * e;
            int d4 = (tid & 15) * 4;
            float4 v = *(const float4*)&g_V[(size_t)(b * LEN + p0 + p) * EMB + h * DH + d4];
            *(uint4*)&sV[p * SVS + d4] = cvt4(v);
        }
        __syncthreads();

        #pragma unroll
        for (int ks = 0; ks < 16; ks++) {
            int kk = ks * 8;
            unsigned a[2][4];
            #pragma unroll
            for (int mi = 0; mi < 2; mi++) {
                int base = (mi * 16 + g) * SSTR + kk + t;
                a[mi][0] = uP[base];
                a[mi][1] = uP[base + 8 * SSTR];
                a[mi][2] = uP[base + 4];
                a[mi][3] = uP[base + 8 * SSTR + 4];
            }
            unsigned b0 = uV[(kk + t) * SVS + wid * 8 + g];
            unsigned b1 = uV[(kk + t + 4) * SVS + wid * 8 + g];
            mma8(cv[0], a[0][0], a[0][1], a[0][2], a[0][3], b0, b1);
            mma8(cv[1], a[1][0], a[1][1], a[1][2], a[1][3], b0, b1);
        }
        __syncthreads();
    }

    #pragma unroll
    for (int mi = 0; mi < 2; mi++) {
        int row = l0 + mi * 16 + g;
        int col = h * DH + wid * 8 + 2 * t;
        float2 v0 = make_float2(cv[mi][0], cv[mi][1]);
        float2 v1 = make_float2(cv[mi][2], cv[mi][3]);
        *(float2*)&g_Val[(size_t)(b * LEN + row) * EMB + col]     = v0;
        *(float2*)&g_Val[(size_t)(b * LEN + row + 8) * EMB + col] = v1;
    }
}

// ---------------------------------------------------------------------------
// Kernel 3: out projection (unchanged)
// ---------------------------------------------------------------------------
__global__ __launch_bounds__(256) void proj_mma(
    const float* __restrict__ bo, const float* __restrict__ x)
{
    __shared__ unsigned As[128 * AS_STRIDE];
    __shared__ unsigned Bs[32 * BS_STRIDE];

    int tid = threadIdx.x;
    int wid = tid >> 5, lane = tid & 31;
    int wm = wid & 3, wn = wid >> 2;
    unsigned g = lane >> 2, t = lane & 3;

    int rowbase = blockIdx.y * 128;
    int nbase   = blockIdx.x * 64;

    float acc[2][4][4] = {};

    for (int kb = 0; kb < EMB; kb += 32) {
        #pragma unroll
        for (int e = 0; e < 4; e++) {
            int r  = (tid >> 3) + 32 * e;
            int c4 = (tid & 7) * 4;
            float4 v = *(const float4*)&g_Val[(size_t)(rowbase + r) * EMB + kb + c4];
            *(uint4*)&As[r * AS_STRIDE + c4] = cvt4(v);
        }
        #pragma unroll
        for (int e = 0; e < 2; e++) {
            int k  = (tid >> 4) + 16 * e;
            int c4 = (tid & 15) * 4;
            float4 v = *(const float4*)&g_WoT[(size_t)(kb + k) * EMB + nbase + c4];
            *(uint4*)&Bs[k * BS_STRIDE + c4] = cvt4(v);
        }
        __syncthreads();

        #pragma unroll
        for (int ks = 0; ks < 4; ks++) {
            int k0 = ks * 8;
            unsigned a[2][4];
            #pragma unroll
            for (int mi = 0; mi < 2; mi++) {
                int base = (wm * 32 + mi * 16 + g) * AS_STRIDE + k0 + t;
                a[mi][0] = As[base];
                a[mi][1] = As[base + 8 * AS_STRIDE];
                a[mi][2] = As[base + 4];
                a[mi][3] = As[base + 8 * AS_STRIDE + 4];
            }
            unsigned b[4][2];
            #pragma unroll
            for (int ni = 0; ni < 4; ni++) {
                int cb = wn * 32 + ni * 8 + g;
                b[ni][0] = Bs[(k0 + t) * BS_STRIDE + cb];
                b[ni][1] = Bs[(k0 + t + 4) * BS_STRIDE + cb];
            }
            #pragma unroll
            for (int mi = 0; mi < 2; mi++)
                #pragma unroll
                for (int ni = 0; ni < 4; ni++)
                    mma8(acc[mi][ni], a[mi][0], a[mi][1], a[mi][2], a[mi][3],
                         b[ni][0], b[ni][1]);
        }
        __syncthreads();
    }

    #pragma unroll
    for (int mi = 0; mi < 2; mi++) {
        int row = rowbase + wm * 32 + mi * 16 + g;
        #pragma unroll
        for (int ni = 0; ni < 4; ni++) {
            int col = nbase + wn * 32 + ni * 8 + 2 * t;
            float b0 = bo[col], b1 = bo[col + 1];
            float2 x0 = *(const float2*)&x[(size_t)row * EMB + col];
            float2 x1 = *(const float2*)&x[(size_t)(row + 8) * EMB + col];
            float2 v0 = make_float2(acc[mi][ni][0] + b0 + x0.x, acc[mi][ni][1] + b1 + x0.y);
            float2 v1 = make_float2(acc[mi][ni][2] + b0 + x1.x, acc[mi][ni][3] + b1 + x1.y);
            *(float2*)&g_Y[(size_t)row * EMB + col]       = v0;
            *(float2*)&g_Y[(size_t)(row + 8) * EMB + col] = v1;
        }
    }
}

// ---------------------------------------------------------------------------
// Kernel 4: row LayerNorm (unchanged)
// ---------------------------------------------------------------------------
__global__ __launch_bounds__(256) void ln_kernel(
    const float* __restrict__ gamma, const float* __restrict__ beta,
    float* __restrict__ out)
{
    int r = blockIdx.x;
    const float* row = g_Y + (size_t)r * EMB;
    int tid = threadIdx.x;

    float v[4];
    float s = 0.0f, s2 = 0.0f;
    #pragma unroll
    for (int e = 0; e < 4; e++) {
        v[e] = row[tid + e * 256];
        s  += v[e];
        s2 += v[e] * v[e];
    }
    __shared__ float rs[8], rs2[8];
    #pragma unroll
    for (int o = 16; o; o >>= 1) {
        s  += __shfl_xor_sync(0xffffffffu, s,  o);
        s2 += __shfl_xor_sync(0xffffffffu, s2, o);
    }
    if ((tid & 31) == 0) { rs[tid >> 5] = s; rs2[tid >> 5] = s2; }
    __syncthreads();
    if (tid < 32) {
        float a = (tid < 8) ? rs[tid]  : 0.0f;
        float c = (tid < 8) ? rs2[tid] : 0.0f;
        #pragma unroll
        for (int o = 4; o; o >>= 1) {
            a += __shfl_xor_sync(0xffffffffu, a, o);
            c += __shfl_xor_sync(0xffffffffu, c, o);
        }
        if (tid == 0) { rs[0] = a; rs2[0] = c; }
    }
    __syncthreads();
    float mu  = rs[0] * (1.0f / 1024.0f);
    float var = rs2[0] * (1.0f / 1024.0f) - mu * mu;
    float inv = rsqrtf(var + 1e-5f);
    #pragma unroll
    for (int e = 0; e < 4; e++) {
        int c = tid + e * 256;
        out[(size_t)r * EMB + c] = (v[e] - mu) * inv * gamma[c] + beta[c];
    }
}

// ---------------------------------------------------------------------------
extern "C" void kernel_launch(void* const* d_in, const int* in_sizes, int n_in,
                              void* d_out, int out_size)
{
    const float* x     = (const float*)d_in[0];
    const int*   mask  = (const int*)  d_in[1];
    const float* Wq    = (const float*)d_in[2];
    const float* bq    = (const float*)d_in[3];
    const float* Wk    = (const float*)d_in[4];
    const float* bk    = (const float*)d_in[5];
    const float* Wv    = (const float*)d_in[6];
    const float* bv    = (const float*)d_in[7];
    const float* Wo    = (const float*)d_in[8];
    const float* bo    = (const float*)d_in[9];
    const float* gamma = (const float*)d_in[10];
    const float* beta  = (const float*)d_in[11];

    float* out   = (float*)d_out;                 // [4,1024,1024]
    float* atten = out + (size_t)BL * EMB;        // [4,16,1024,1024]

    const int SCORE_SMEM = (32 * SQS + 64 * SKTS + 32 * SSTR + 1024 + 64) * (int)sizeof(float);
    const int PV_SMEM    = (32 * SSTR + 128 * SVS + 64) * (int)sizeof(float);
    cudaFuncSetAttribute(score_kernel,
                         cudaFuncAttributeMaxDynamicSharedMemorySize, SCORE_SMEM);
    cudaFuncSetAttribute(pv_kernel,
                         cudaFuncAttributeMaxDynamicSharedMemorySize, PV_SMEM);

    transpose_wo<<<dim3(32, 32), dim3(32, 8)>>>(Wo);
    qkv_mma<<<dim3(16, 32, 3), dim3(256)>>>(x, Wq, bq, Wk, bk, Wv, bv);
    transpose_k<<<dim3(32, 2, 64), dim3(32, 8)>>>();
    score_kernel<<<dim3(32, 64), dim3(256), SCORE_SMEM>>>(mask, atten);
    pv_kernel<<<dim3(32, 64), dim3(256), PV_SMEM>>>(atten);
    proj_mma<<<dim3(16, 32), dim3(256)>>>(bo, x);
    ln_kernel<<<BL, 256>>>(gamma, beta, out);
}

// round 4
// speedup vs baseline: 2.0923x; 2.0923x over previous
#include <cuda_runtime.h>
#include <math.h>

#define BLC 4
#define LEN 1024
#define HN 16
#define DH 64
#define EMB 1024
#define BL (BLC*LEN)          // 4096 rows total
#define MINV (-1.7014117e38f) // float32 min / 2

// Scratch (allocation-free rule: __device__ globals)
__device__ float g_Q[BL*EMB];
__device__ float g_K[BL*EMB];
__device__ float g_V[BL*EMB];
__device__ float g_KT[BL*EMB];     // [b*16+h][64 d][1024 pos]
__device__ float g_WoT[EMB*EMB];   // Wo transposed: [k][n]
__device__ float g_Val[BL*EMB];
__device__ float g_Y[BL*EMB];

// ---------------------------------------------------------------------------
// tf32 + fast-exp helpers
// ---------------------------------------------------------------------------
__device__ __forceinline__ unsigned f2tf(float f) {
    unsigned u; asm("cvt.rna.tf32.f32 %0, %1;" : "=r"(u) : "f"(f)); return u;
}
__device__ __forceinline__ uint4 cvt4(float4 v) {
    uint4 u; u.x = f2tf(v.x); u.y = f2tf(v.y); u.z = f2tf(v.z); u.w = f2tf(v.w); return u;
}
__device__ __forceinline__ void mma8(float* c,
                                     unsigned a0, unsigned a1, unsigned a2, unsigned a3,
                                     unsigned b0, unsigned b1) {
    asm volatile(
        "mma.sync.aligned.m16n8k8.row.col.f32.tf32.tf32.f32 "
        "{%0,%1,%2,%3}, {%4,%5,%6,%7}, {%8,%9}, {%0,%1,%2,%3};"
        : "+f"(c[0]), "+f"(c[1]), "+f"(c[2]), "+f"(c[3])
        : "r"(a0), "r"(a1), "r"(a2), "r"(a3), "r"(b0), "r"(b1));
}

// e^x on the FMA pipe (no MUFU). Accurate to ~3e-6 rel. Handles x << 0 -> ~0.
__device__ __forceinline__ float fexp(float x) {
    float y = fmaxf(x * 1.4426950408889634f, -126.0f);
    float tmagic = y + 12582912.0f;          // round-to-nearest-int (|y| < 2^22)
    float r = tmagic - 12582912.0f;
    float f = y - r;                         // f in [-0.5, 0.5]
    int   e = __float_as_int(tmagic);        // low bits = int(y) + 0x4B400000
    float p = 1.33335581e-3f;
    p = fmaf(p, f, 9.61812910e-3f);
    p = fmaf(p, f, 5.55041087e-2f);
    p = fmaf(p, f, 2.40226507e-1f);
    p = fmaf(p, f, 6.93147180e-1f);
    p = fmaf(p, f, 1.0f);
    float s = __int_as_float((e + (127 - 0x4B400000)) << 23);
    return p * s;
}

// ---------------------------------------------------------------------------
// Kernel 1: QKV projections via tf32 mma (unchanged, known-good)
// ---------------------------------------------------------------------------
#define AS_STRIDE 36
#define BS_STRIDE 72

__global__ __launch_bounds__(256) void qkv_mma(
    const float* __restrict__ x,
    const float* __restrict__ Wq, const float* __restrict__ bq,
    const float* __restrict__ Wk, const float* __restrict__ bk,
    const float* __restrict__ Wv, const float* __restrict__ bv)
{
    const float* W; const float* bias; float* out;
    int z = blockIdx.z;
    if (z == 0)      { W = Wq; bias = bq; out = g_Q; }
    else if (z == 1) { W = Wk; bias = bk; out = g_K; }
    else             { W = Wv; bias = bv; out = g_V; }

    __shared__ unsigned As[128 * AS_STRIDE];
    __shared__ unsigned Bs[32 * BS_STRIDE];

    int tid = threadIdx.x;
    int wid = tid >> 5, lane = tid & 31;
    int wm = wid & 3, wn = wid >> 2;
    unsigned g = lane >> 2, t = lane & 3;

    int rowbase = blockIdx.y * 128;
    int head    = blockIdx.x;

    float acc[2][4][4] = {};

    for (int kb = 0; kb < EMB; kb += 32) {
        #pragma unroll
        for (int e = 0; e < 4; e++) {
            int r  = (tid >> 3) + 32 * e;
            int c4 = (tid & 7) * 4;
            float4 v = *(const float4*)&x[(size_t)(rowbase + r) * EMB + kb + c4];
            *(uint4*)&As[r * AS_STRIDE + c4] = cvt4(v);
        }
        #pragma unroll
        for (int e = 0; e < 2; e++) {
            int k  = (tid >> 4) + 16 * e;
            int c4 = (tid & 15) * 4;
            float4 v = *(const float4*)&W[(size_t)head * (EMB * DH) + (size_t)(kb + k) * DH + c4];
            *(uint4*)&Bs[k * BS_STRIDE + c4] = cvt4(v);
        }
        __syncthreads();

        #pragma unroll
        for (int ks = 0; ks < 4; ks++) {
            int k0 = ks * 8;
            unsigned a[2][4];
            #pragma unroll
            for (int mi = 0; mi < 2; mi++) {
                int base = (wm * 32 + mi * 16 + g) * AS_STRIDE + k0 + t;
                a[mi][0] = As[base];
                a[mi][1] = As[base + 8 * AS_STRIDE];
                a[mi][2] = As[base + 4];
                a[mi][3] = As[base + 8 * AS_STRIDE + 4];
            }
            unsigned b[4][2];
            #pragma unroll
            for (int ni = 0; ni < 4; ni++) {
                int cb = wn * 32 + ni * 8 + g;
                b[ni][0] = Bs[(k0 + t) * BS_STRIDE + cb];
                b[ni][1] = Bs[(k0 + t + 4) * BS_STRIDE + cb];
            }
            #pragma unroll
            for (int mi = 0; mi < 2; mi++)
                #pragma unroll
                for (int ni = 0; ni < 4; ni++)
                    mma8(acc[mi][ni], a[mi][0], a[mi][1], a[mi][2], a[mi][3],
                         b[ni][0], b[ni][1]);
        }
        __syncthreads();
    }

    #pragma unroll
    for (int mi = 0; mi < 2; mi++) {
        int row = rowbase + wm * 32 + mi * 16 + g;
        #pragma unroll
        for (int ni = 0; ni < 4; ni++) {
            int col = head * 64 + wn * 32 + ni * 8 + 2 * t;
            float b0 = bias[col], b1 = bias[col + 1];
            float2 v0 = make_float2(acc[mi][ni][0] + b0, acc[mi][ni][1] + b1);
            float2 v1 = make_float2(acc[mi][ni][2] + b0, acc[mi][ni][3] + b1);
            *(float2*)&out[(size_t)row * EMB + col]       = v0;
            *(float2*)&out[(size_t)(row + 8) * EMB + col] = v1;
        }
    }
}

// ---------------------------------------------------------------------------
// Transposes (unchanged)
// ---------------------------------------------------------------------------
__global__ void transpose_k() {
    __shared__ float tl[32][33];
    int bh = blockIdx.z;
    int b = bh >> 4, h = bh & 15;
    int p0 = blockIdx.x * 32, d0 = blockIdx.y * 32;
    int tx = threadIdx.x, ty = threadIdx.y;
    #pragma unroll
    for (int j = 0; j < 4; j++)
        tl[ty + 8 * j][tx] =
            g_K[(size_t)(b * LEN + p0 + ty + 8 * j) * EMB + h * DH + d0 + tx];
    __syncthreads();
    #pragma unroll
    for (int j = 0; j < 4; j++)
        g_KT[((size_t)bh * DH + d0 + ty + 8 * j) * LEN + p0 + tx] = tl[tx][ty + 8 * j];
}

__global__ void transpose_wo(const float* __restrict__ Wo) {
    __shared__ float tl[32][33];
    int n0 = blockIdx.y * 32, k0 = blockIdx.x * 32;
    int tx = threadIdx.x, ty = threadIdx.y;
    #pragma unroll
    for (int j = 0; j < 4; j++)
        tl[ty + 8 * j][tx] = Wo[(size_t)(n0 + ty + 8 * j) * EMB + k0 + tx];
    __syncthreads();
    #pragma unroll
    for (int j = 0; j < 4; j++)
        g_WoT[(size_t)(k0 + ty + 8 * j) * EMB + n0 + tx] = tl[tx][ty + 8 * j];
}

// ---------------------------------------------------------------------------
// Kernel 2: fully fused flash attention.
// Per block: one (b,h), 32 q-rows.
// Pass A: S chunks in registers -> online row max/sum (no smem S).
// Pass B: recompute S, p = fexp(s-m)/l -> atten gmem (final) + perm store ->
//         PV mma accumulate -> g_Val.
// Q and P operands live in smem in mma-fragment-permuted order (LDS.128 loads).
// ---------------------------------------------------------------------------
#define KTS 136   // K^T chunk stride (==8 mod 32)
#define VS  72    // V chunk stride   (==8 mod 32)

__global__ __launch_bounds__(256, 3) void flash_kernel(
    const int* __restrict__ mask, float* __restrict__ atten)
{
    extern __shared__ float sm[];
    float* sQp  = sm;               // 2048: perm Q (8 ks x 2 mi x 128)
    float* sPp  = sQp + 2048;       // 4096: perm P (16 ks x 2 mi x 128)
    float* sBuf = sPp + 4096;       // 9216: K^T chunk (64x136) or V chunk (128x72)
    float* sMk  = sBuf + 9216;      // 1024: mask as float
    float* sM   = sMk + 1024;       // 32: running row max
    float* sL   = sM + 32;          // 32: running row denom
    float* sR   = sL + 32;          // 32: per-chunk rescale
    float* sCM  = sR + 32;          // 256: per-warp chunk max
    float* sCS  = sCM + 256;        // 256: per-warp chunk sum
    // total 16992 floats = 67968 B

    int tile = blockIdx.x, bh = blockIdx.y;
    int b = bh >> 4, h = bh & 15;
    int l0 = tile * 32;
    int tid = threadIdx.x;
    int wid = tid >> 5, lane = tid & 31;
    int g = lane >> 2, t = lane & 3;

    // ---- Stage Q in fragment-permuted order ----
    #pragma unroll
    for (int e = 0; e < 8; e++) {
        int idx = tid + 256 * e;
        int r = idx >> 6, d = idx & 63;
        float q = g_Q[(size_t)(b * LEN + l0 + r) * EMB + h * DH + d];
        int mi = r >> 4, gg = r & 7, jl = (r >> 3) & 1;
        int ksq = d >> 3, tt = d & 3, jh = (d >> 2) & 1;
        sQp[(((ksq << 1) + mi) << 7) + (((gg << 2) | tt) << 2) + (jl + 2 * jh)] =
            __uint_as_float(f2tf(q));
    }
    #pragma unroll
    for (int e = 0; e < 4; e++) {
        int c = tid + 256 * e;
        sMk[c] = (float)mask[b * LEN + c];
    }
    if (tid < 32) { sM[tid] = -3.4e38f; sL[tid] = 0.0f; }
    __syncthreads();

    const unsigned* uQp  = (const unsigned*)sQp;
    const unsigned* uPp  = (const unsigned*)sPp;
    const unsigned* uBuf = (const unsigned*)sBuf;
    const float scale = 0.125f;

    // ================= PASS A: online max/sum =================
    for (int kt = 0; kt < 8; kt++) {
        int p0 = kt * 128;
        #pragma unroll
        for (int e = 0; e < 8; e++) {
            int d = (tid >> 5) + 8 * e, p4 = (tid & 31) * 4;
            float4 v = *(const float4*)&g_KT[((size_t)bh * DH + d) * LEN + p0 + p4];
            *(uint4*)&sBuf[d * KTS + p4] = cvt4(v);
        }
        __syncthreads();

        float c[2][2][4] = {};
        #pragma unroll
        for (int ks = 0; ks < 8; ks++) {
            uint4 A0 = *(const uint4*)&uQp[((ks * 2 + 0) << 7) + (lane << 2)];
            uint4 A1 = *(const uint4*)&uQp[((ks * 2 + 1) << 7) + (lane << 2)];
            #pragma unroll
            for (int ni = 0; ni < 2; ni++) {
                int cb = wid * 16 + ni * 8 + g;
                unsigned b0 = uBuf[(ks * 8 + t) * KTS + cb];
                unsigned b1 = uBuf[(ks * 8 + t + 4) * KTS + cb];
                mma8(c[0][ni], A0.x, A0.y, A0.z, A0.w, b0, b1);
                mma8(c[1][ni], A1.x, A1.y, A1.z, A1.w, b0, b1);
            }
        }

        // mask + scale in regs, per-row chunk max
        float mx[2][2] = {{-3.4e38f, -3.4e38f}, {-3.4e38f, -3.4e38f}};
        #pragma unroll
        for (int mi = 0; mi < 2; mi++)
            #pragma unroll
            for (int ni = 0; ni < 2; ni++) {
                int colg = p0 + wid * 16 + ni * 8 + 2 * t;
                float k0m = sMk[colg], k1m = sMk[colg + 1];
                float* cc = c[mi][ni];
                cc[0] = (k0m != 0.0f) ? cc[0] * scale : MINV;
                cc[1] = (k1m != 0.0f) ? cc[1] * scale : MINV;
                cc[2] = (k0m != 0.0f) ? cc[2] * scale : MINV;
                cc[3] = (k1m != 0.0f) ? cc[3] * scale : MINV;
                mx[mi][0] = fmaxf(mx[mi][0], fmaxf(cc[0], cc[1]));
                mx[mi][1] = fmaxf(mx[mi][1], fmaxf(cc[2], cc[3]));
            }
        #pragma unroll
        for (int mi = 0; mi < 2; mi++)
            #pragma unroll
            for (int jl = 0; jl < 2; jl++) {
                float v = mx[mi][jl];
                v = fmaxf(v, __shfl_xor_sync(0xffffffffu, v, 1));
                v = fmaxf(v, __shfl_xor_sync(0xffffffffu, v, 2));
                if (t == 0) sCM[wid * 32 + mi * 16 + jl * 8 + g] = v;
            }
        __syncthreads();
        if (tid < 32) {
            float mo = sM[tid], m = mo;
            #pragma unroll
            for (int w = 0; w < 8; w++) m = fmaxf(m, sCM[w * 32 + tid]);
            sR[tid] = fexp(mo - m);
            sM[tid] = m;
        }
        __syncthreads();

        // chunk sums with updated m
        float sums[2][2] = {};
        #pragma unroll
        for (int mi = 0; mi < 2; mi++) {
            float mA = sM[mi * 16 + g], mB = sM[mi * 16 + 8 + g];
            #pragma unroll
            for (int ni = 0; ni < 2; ni++) {
                float* cc = c[mi][ni];
                sums[mi][0] += fexp(cc[0] - mA) + fexp(cc[1] - mA);
                sums[mi][1] += fexp(cc[2] - mB) + fexp(cc[3] - mB);
            }
        }
        #pragma unroll
        for (int mi = 0; mi < 2; mi++)
            #pragma unroll
            for (int jl = 0; jl < 2; jl++) {
                float v = sums[mi][jl];
                v += __shfl_xor_sync(0xffffffffu, v, 1);
                v += __shfl_xor_sync(0xffffffffu, v, 2);
                if (t == 0) sCS[wid * 32 + mi * 16 + jl * 8 + g] = v;
            }
        __syncthreads();
        if (tid < 32) {
            float s = 0.0f;
            #pragma unroll
            for (int w = 0; w < 8; w++) s += sCS[w * 32 + tid];
            sL[tid] = sL[tid] * sR[tid] + s;
        }
        __syncthreads();
    }

    // per-thread final row stats (rows g, g+8, g+16, g+24)
    float rowm[2][2], rowli[2][2];
    #pragma unroll
    for (int mi = 0; mi < 2; mi++)
        #pragma unroll
        for (int jl = 0; jl < 2; jl++) {
            int r = mi * 16 + jl * 8 + g;
            rowm[mi][jl]  = sM[r];
            rowli[mi][jl] = 1.0f / sL[r];
        }

    // ================= PASS B: final p -> atten + PV =================
    float cv[2][4] = {};
    for (int kt = 0; kt < 8; kt++) {
        int p0 = kt * 128;
        #pragma unroll
        for (int e = 0; e < 8; e++) {
            int d = (tid >> 5) + 8 * e, p4 = (tid & 31) * 4;
            float4 v = *(const float4*)&g_KT[((size_t)bh * DH + d) * LEN + p0 + p4];
            *(uint4*)&sBuf[d * KTS + p4] = cvt4(v);
        }
        __syncthreads();

        float c[2][2][4] = {};
        #pragma unroll
        for (int ks = 0; ks < 8; ks++) {
            uint4 A0 = *(const uint4*)&uQp[((ks * 2 + 0) << 7) + (lane << 2)];
            uint4 A1 = *(const uint4*)&uQp[((ks * 2 + 1) << 7) + (lane << 2)];
            #pragma unroll
            for (int ni = 0; ni < 2; ni++) {
                int cb = wid * 16 + ni * 8 + g;
                unsigned b0 = uBuf[(ks * 8 + t) * KTS + cb];
                unsigned b1 = uBuf[(ks * 8 + t + 4) * KTS + cb];
                mma8(c[0][ni], A0.x, A0.y, A0.z, A0.w, b0, b1);
                mma8(c[1][ni], A1.x, A1.y, A1.z, A1.w, b0, b1);
            }
        }

        // epilogue: final probabilities -> gmem atten + perm store to sPp
        #pragma unroll
        for (int mi = 0; mi < 2; mi++)
            #pragma unroll
            for (int ni = 0; ni < 2; ni++) {
                int colg = p0 + wid * 16 + ni * 8 + 2 * t;
                float k0m = sMk[colg], k1m = sMk[colg + 1];
                float* cc = c[mi][ni];
                float s0 = (k0m != 0.0f) ? cc[0] * scale : MINV;
                float s1 = (k1m != 0.0f) ? cc[1] * scale : MINV;
                float s2 = (k0m != 0.0f) ? cc[2] * scale : MINV;
                float s3 = (k1m != 0.0f) ? cc[3] * scale : MINV;
                float pv0 = fexp(s0 - rowm[mi][0]) * rowli[mi][0];
                float pv1 = fexp(s1 - rowm[mi][0]) * rowli[mi][0];
                float pv2 = fexp(s2 - rowm[mi][1]) * rowli[mi][1];
                float pv3 = fexp(s3 - rowm[mi][1]) * rowli[mi][1];
                int row0 = l0 + mi * 16 + g;
                float* arow0 = atten + ((size_t)bh * LEN + row0) * LEN + colg;
                float* arow1 = atten + ((size_t)bh * LEN + row0 + 8) * LEN + colg;
                *(float2*)arow0 = make_float2(pv0, pv1);
                *(float2*)arow1 = make_float2(pv2, pv3);
                // permuted store (A-fragment order for PV mma)
                int base = (((wid * 2 + ni) * 2 + mi) << 7);
                int a0a = base + ((g * 4 + 2 * (t & 1)) << 2) + ((t >> 1) << 1);
                sPp[a0a]     = __uint_as_float(f2tf(pv0));
                sPp[a0a + 4] = __uint_as_float(f2tf(pv1));
                sPp[a0a + 1] = __uint_as_float(f2tf(pv2));
                sPp[a0a + 5] = __uint_as_float(f2tf(pv3));
            }
        __syncthreads();

        // stage V chunk [128 pos][64 d] (overwrites K^T)
        #pragma unroll
        for (int e = 0; e < 8; e++) {
            int p = (tid >> 4) + 16 * e, d4 = (tid & 15) * 4;
            float4 v = *(const float4*)&g_V[(size_t)(b * LEN + p0 + p) * EMB + h * DH + d4];
            *(uint4*)&sBuf[p * VS + d4] = cvt4(v);
        }
        __syncthreads();

        // PV mma
        #pragma unroll
        for (int ks = 0; ks < 16; ks++) {
            uint4 A0 = *(const uint4*)&uPp[((ks * 2 + 0) << 7) + (lane << 2)];
            uint4 A1 = *(const uint4*)&uPp[((ks * 2 + 1) << 7) + (lane << 2)];
            unsigned b0 = uBuf[(ks * 8 + t) * VS + wid * 8 + g];
            unsigned b1 = uBuf[(ks * 8 + t + 4) * VS + wid * 8 + g];
            mma8(cv[0], A0.x, A0.y, A0.z, A0.w, b0, b1);
            mma8(cv[1], A1.x, A1.y, A1.z, A1.w, b0, b1);
        }
        __syncthreads();
    }

    // write O (already normalized: li folded into p)
    #pragma unroll
    for (int mi = 0; mi < 2; mi++) {
        int row = l0 + mi * 16 + g;
        int col = h * DH + wid * 8 + 2 * t;
        *(float2*)&g_Val[(size_t)(b * LEN + row) * EMB + col] =
            make_float2(cv[mi][0], cv[mi][1]);
        *(float2*)&g_Val[(size_t)(b * LEN + row + 8) * EMB + col] =
            make_float2(cv[mi][2], cv[mi][3]);
    }
}

// ---------------------------------------------------------------------------
// Kernel 3: out projection (unchanged)
// ---------------------------------------------------------------------------
__global__ __launch_bounds__(256) void proj_mma(
    const float* __restrict__ bo, const float* __restrict__ x)
{
    __shared__ unsigned As[128 * AS_STRIDE];
    __shared__ unsigned Bs[32 * BS_STRIDE];

    int tid = threadIdx.x;
    int wid = tid >> 5, lane = tid & 31;
    int wm = wid & 3, wn = wid >> 2;
    unsigned g = lane >> 2, t = lane & 3;

    int rowbase = blockIdx.y * 128;
    int nbase   = blockIdx.x * 64;

    float acc[2][4][4] = {};

    for (int kb = 0; kb < EMB; kb += 32) {
        #pragma unroll
        for (int e = 0; e < 4; e++) {
            int r  = (tid >> 3) + 32 * e;
            int c4 = (tid & 7) * 4;
            float4 v = *(const float4*)&g_Val[(size_t)(rowbase + r) * EMB + kb + c4];
            *(uint4*)&As[r * AS_STRIDE + c4] = cvt4(v);
        }
        #pragma unroll
        for (int e = 0; e < 2; e++) {
            int k  = (tid >> 4) + 16 * e;
            int c4 = (tid & 15) * 4;
            float4 v = *(const float4*)&g_WoT[(size_t)(kb + k) * EMB + nbase + c4];
            *(uint4*)&Bs[k * BS_STRIDE + c4] = cvt4(v);
        }
        __syncthreads();

        #pragma unroll
        for (int ks = 0; ks < 4; ks++) {
            int k0 = ks * 8;
            unsigned a[2][4];
            #pragma unroll
            for (int mi = 0; mi < 2; mi++) {
                int base = (wm * 32 + mi * 16 + g) * AS_STRIDE + k0 + t;
                a[mi][0] = As[base];
                a[mi][1] = As[base + 8 * AS_STRIDE];
                a[mi][2] = As[base + 4];
                a[mi][3] = As[base + 8 * AS_STRIDE + 4];
            }
            unsigned b[4][2];
            #pragma unroll
            for (int ni = 0; ni < 4; ni++) {
                int cb = wn * 32 + ni * 8 + g;
                b[ni][0] = Bs[(k0 + t) * BS_STRIDE + cb];
                b[ni][1] = Bs[(k0 + t + 4) * BS_STRIDE + cb];
            }
            #pragma unroll
            for (int mi = 0; mi < 2; mi++)
                #pragma unroll
                for (int ni = 0; ni < 4; ni++)
                    mma8(acc[mi][ni], a[mi][0], a[mi][1], a[mi][2], a[mi][3],
                         b[ni][0], b[ni][1]);
        }
        __syncthreads();
    }

    #pragma unroll
    for (int mi = 0; mi < 2; mi++) {
        int row = rowbase + wm * 32 + mi * 16 + g;
        #pragma unroll
        for (int ni = 0; ni < 4; ni++) {
            int col = nbase + wn * 32 + ni * 8 + 2 * t;
            float b0 = bo[col], b1 = bo[col + 1];
            float2 x0 = *(const float2*)&x[(size_t)row * EMB + col];
            float2 x1 = *(const float2*)&x[(size_t)(row + 8) * EMB + col];
            float2 v0 = make_float2(acc[mi][ni][0] + b0 + x0.x, acc[mi][ni][1] + b1 + x0.y);
            float2 v1 = make_float2(acc[mi][ni][2] + b0 + x1.x, acc[mi][ni][3] + b1 + x1.y);
            *(float2*)&g_Y[(size_t)row * EMB + col]       = v0;
            *(float2*)&g_Y[(size_t)(row + 8) * EMB + col] = v1;
        }
    }
}

// ---------------------------------------------------------------------------
// Kernel 4: row LayerNorm (unchanged)
// ---------------------------------------------------------------------------
__global__ __launch_bounds__(256) void ln_kernel(
    const float* __restrict__ gamma, const float* __restrict__ beta,
    float* __restrict__ out)
{
    int r = blockIdx.x;
    const float* row = g_Y + (size_t)r * EMB;
    int tid = threadIdx.x;

    float v[4];
    float s = 0.0f, s2 = 0.0f;
    #pragma unroll
    for (int e = 0; e < 4; e++) {
        v[e] = row[tid + e * 256];
        s  += v[e];
        s2 += v[e] * v[e];
    }
    __shared__ float rs[8], rs2[8];
    #pragma unroll
    for (int o = 16; o; o >>= 1) {
        s  += __shfl_xor_sync(0xffffffffu, s,  o);
        s2 += __shfl_xor_sync(0xffffffffu, s2, o);
    }
    if ((tid & 31) == 0) { rs[tid >> 5] = s; rs2[tid >> 5] = s2; }
    __syncthreads();
    if (tid < 32) {
        float a = (tid < 8) ? rs[tid]  : 0.0f;
        float c = (tid < 8) ? rs2[tid] : 0.0f;
        #pragma unroll
        for (int o = 4; o; o >>= 1) {
            a += __shfl_xor_sync(0xffffffffu, a, o);
            c += __shfl_xor_sync(0xffffffffu, c, o);
        }
        if (tid == 0) { rs[0] = a; rs2[0] = c; }
    }
    __syncthreads();
    float mu  = rs[0] * (1.0f / 1024.0f);
    float var = rs2[0] * (1.0f / 1024.0f) - mu * mu;
    float inv = rsqrtf(var + 1e-5f);
    #pragma unroll
    for (int e = 0; e < 4; e++) {
        int c = tid + e * 256;
        out[(size_t)r * EMB + c] = (v[e] - mu) * inv * gamma[c] + beta[c];
    }
}

// ---------------------------------------------------------------------------
extern "C" void kernel_launch(void* const* d_in, const int* in_sizes, int n_in,
                              void* d_out, int out_size)
{
    const float* x     = (const float*)d_in[0];
    const int*   mask  = (const int*)  d_in[1];
    const float* Wq    = (const float*)d_in[2];
    const float* bq    = (const float*)d_in[3];
    const float* Wk    = (const float*)d_in[4];
    const float* bk    = (const float*)d_in[5];
    const float* Wv    = (const float*)d_in[6];
    const float* bv    = (const float*)d_in[7];
    const float* Wo    = (const float*)d_in[8];
    const float* bo    = (const float*)d_in[9];
    const float* gamma = (const float*)d_in[10];
    const float* beta  = (const float*)d_in[11];

    float* out   = (float*)d_out;                 // [4,1024,1024]
    float* atten = out + (size_t)BL * EMB;        // [4,16,1024,1024]

    const int FLASH_SMEM = 16992 * (int)sizeof(float);
    cudaFuncSetAttribute(flash_kernel,
                         cudaFuncAttributeMaxDynamicSharedMemorySize, FLASH_SMEM);

    transpose_wo<<<dim3(32, 32), dim3(32, 8)>>>(Wo);
    qkv_mma<<<dim3(16, 32, 3), dim3(256)>>>(x, Wq, bq, Wk, bk, Wv, bv);
    transpose_k<<<dim3(32, 2, 64), dim3(32, 8)>>>();
    flash_kernel<<<dim3(32, 64), dim3(256), FLASH_SMEM>>>(mask, atten);
    proj_mma<<<dim3(16, 32), dim3(256)>>>(bo, x);
    ln_kernel<<<BL, 256>>>(gamma, beta, out);
}

// round 5
// speedup vs baseline: 2.3848x; 1.1398x over previous
#include <cuda_runtime.h>
#include <math.h>

#define BLC 4
#define LEN 1024
#define HN 16
#define DH 64
#define EMB 1024
#define BL (BLC*LEN)          // 4096 rows total
#define MINV (-1.7014117e38f) // float32 min / 2

// Scratch (allocation-free rule: __device__ globals)
__device__ float g_Q[BL*EMB];
__device__ float g_K[BL*EMB];
__device__ float g_V[BL*EMB];
__device__ float g_KT[BL*EMB];     // [b*16+h][64 d][1024 pos]
__device__ float g_WoT[EMB*EMB];   // Wo transposed: [k][n]
__device__ float g_Val[BL*EMB];
__device__ float g_Y[BL*EMB];

// ---------------------------------------------------------------------------
// tf32 + fast-exp helpers
// ---------------------------------------------------------------------------
__device__ __forceinline__ unsigned f2tf(float f) {
    unsigned u; asm("cvt.rna.tf32.f32 %0, %1;" : "=r"(u) : "f"(f)); return u;
}
__device__ __forceinline__ uint4 cvt4(float4 v) {
    uint4 u; u.x = f2tf(v.x); u.y = f2tf(v.y); u.z = f2tf(v.z); u.w = f2tf(v.w); return u;
}
__device__ __forceinline__ void mma8(float* c,
                                     unsigned a0, unsigned a1, unsigned a2, unsigned a3,
                                     unsigned b0, unsigned b1) {
    asm volatile(
        "mma.sync.aligned.m16n8k8.row.col.f32.tf32.tf32.f32 "
        "{%0,%1,%2,%3}, {%4,%5,%6,%7}, {%8,%9}, {%0,%1,%2,%3};"
        : "+f"(c[0]), "+f"(c[1]), "+f"(c[2]), "+f"(c[3])
        : "r"(a0), "r"(a1), "r"(a2), "r"(a3), "r"(b0), "r"(b1));
}

// e^x on the FMA pipe (no MUFU). Accurate to ~3e-6 rel. Handles x << 0 -> ~0.
__device__ __forceinline__ float fexp(float x) {
    float y = fmaxf(x * 1.4426950408889634f, -126.0f);
    float tmagic = y + 12582912.0f;          // round-to-nearest-int (|y| < 2^22)
    float r = tmagic - 12582912.0f;
    float f = y - r;                         // f in [-0.5, 0.5]
    int   e = __float_as_int(tmagic);        // low bits = int(y) + 0x4B400000
    float p = 1.33335581e-3f;
    p = fmaf(p, f, 9.61812910e-3f);
    p = fmaf(p, f, 5.55041087e-2f);
    p = fmaf(p, f, 2.40226507e-1f);
    p = fmaf(p, f, 6.93147180e-1f);
    p = fmaf(p, f, 1.0f);
    float s = __int_as_float((e + (127 - 0x4B400000)) << 23);
    return p * s;
}

// ---------------------------------------------------------------------------
// Kernel 1: QKV projections via tf32 mma. Block tile 128m x 128n (2 heads),
// kblock 32. 8 warps: 4(m) x 2(n); warp tile 32x64 = 2 mi x 8 ni frags.
// ---------------------------------------------------------------------------
#define AS_STRIDE 36   // == 4 mod 32
#define BS2 136        // == 8 mod 32

__global__ __launch_bounds__(256) void qkv_mma(
    const float* __restrict__ x,
    const float* __restrict__ Wq, const float* __restrict__ bq,
    const float* __restrict__ Wk, const float* __restrict__ bk,
    const float* __restrict__ Wv, const float* __restrict__ bv)
{
    const float* W; const float* bias; float* out;
    int z = blockIdx.z;
    if (z == 0)      { W = Wq; bias = bq; out = g_Q; }
    else if (z == 1) { W = Wk; bias = bk; out = g_K; }
    else             { W = Wv; bias = bv; out = g_V; }

    __shared__ unsigned As[128 * AS_STRIDE];
    __shared__ unsigned Bs[32 * BS2];

    int tid = threadIdx.x;
    int wid = tid >> 5, lane = tid & 31;
    int wm = wid & 3, wn = wid >> 2;
    unsigned g = lane >> 2, t = lane & 3;

    int rowbase = blockIdx.y * 128;
    int nbase   = blockIdx.x * 128;

    float acc[2][8][4] = {};

    for (int kb = 0; kb < EMB; kb += 32) {
        // Stage A: 128x32
        #pragma unroll
        for (int e = 0; e < 4; e++) {
            int r  = (tid >> 3) + 32 * e;
            int c4 = (tid & 7) * 4;
            float4 v = *(const float4*)&x[(size_t)(rowbase + r) * EMB + kb + c4];
            *(uint4*)&As[r * AS_STRIDE + c4] = cvt4(v);
        }
        // Stage B: 32x128 spanning 2 heads
        #pragma unroll
        for (int e = 0; e < 4; e++) {
            int idx = tid + 256 * e;
            int k   = idx >> 5;
            int c4  = (idx & 31) * 4;
            int head = (nbase + c4) >> 6;
            int hcol = (nbase + c4) & 63;
            float4 v = *(const float4*)&W[(size_t)head * (EMB * DH) + (size_t)(kb + k) * DH + hcol];
            *(uint4*)&Bs[k * BS2 + c4] = cvt4(v);
        }
        __syncthreads();

        #pragma unroll
        for (int ks = 0; ks < 4; ks++) {
            int k0 = ks * 8;
            unsigned a[2][4];
            #pragma unroll
            for (int mi = 0; mi < 2; mi++) {
                int base = (wm * 32 + mi * 16 + g) * AS_STRIDE + k0 + t;
                a[mi][0] = As[base];
                a[mi][1] = As[base + 8 * AS_STRIDE];
                a[mi][2] = As[base + 4];
                a[mi][3] = As[base + 8 * AS_STRIDE + 4];
            }
            #pragma unroll
            for (int ni = 0; ni < 8; ni++) {
                int cb = wn * 64 + ni * 8 + g;
                unsigned b0 = Bs[(k0 + t) * BS2 + cb];
                unsigned b1 = Bs[(k0 + t + 4) * BS2 + cb];
                mma8(acc[0][ni], a[0][0], a[0][1], a[0][2], a[0][3], b0, b1);
                mma8(acc[1][ni], a[1][0], a[1][1], a[1][2], a[1][3], b0, b1);
            }
        }
        __syncthreads();
    }

    #pragma unroll
    for (int mi = 0; mi < 2; mi++) {
        int row = rowbase + wm * 32 + mi * 16 + g;
        #pragma unroll
        for (int ni = 0; ni < 8; ni++) {
            int col = nbase + wn * 64 + ni * 8 + 2 * t;
            float b0 = bias[col], b1 = bias[col + 1];
            *(float2*)&out[(size_t)row * EMB + col] =
                make_float2(acc[mi][ni][0] + b0, acc[mi][ni][1] + b1);
            *(float2*)&out[(size_t)(row + 8) * EMB + col] =
                make_float2(acc[mi][ni][2] + b0, acc[mi][ni][3] + b1);
        }
    }
}

// ---------------------------------------------------------------------------
// Transposes (unchanged)
// ---------------------------------------------------------------------------
__global__ void transpose_k() {
    __shared__ float tl[32][33];
    int bh = blockIdx.z;
    int b = bh >> 4, h = bh & 15;
    int p0 = blockIdx.x * 32, d0 = blockIdx.y * 32;
    int tx = threadIdx.x, ty = threadIdx.y;
    #pragma unroll
    for (int j = 0; j < 4; j++)
        tl[ty + 8 * j][tx] =
            g_K[(size_t)(b * LEN + p0 + ty + 8 * j) * EMB + h * DH + d0 + tx];
    __syncthreads();
    #pragma unroll
    for (int j = 0; j < 4; j++)
        g_KT[((size_t)bh * DH + d0 + ty + 8 * j) * LEN + p0 + tx] = tl[tx][ty + 8 * j];
}

__global__ void transpose_wo(const float* __restrict__ Wo) {
    __shared__ float tl[32][33];
    int n0 = blockIdx.y * 32, k0 = blockIdx.x * 32;
    int tx = threadIdx.x, ty = threadIdx.y;
    #pragma unroll
    for (int j = 0; j < 4; j++)
        tl[ty + 8 * j][tx] = Wo[(size_t)(n0 + ty + 8 * j) * EMB + k0 + tx];
    __syncthreads();
    #pragma unroll
    for (int j = 0; j < 4; j++)
        g_WoT[(size_t)(k0 + ty + 8 * j) * EMB + n0 + tx] = tl[tx][ty + 8 * j];
}

// ---------------------------------------------------------------------------
// Kernel 2: ONE-PASS fused flash attention with deferred atten normalization.
// Per block: one (b,h), 32 q-rows, 8 chunks of 128 key-positions.
// Per chunk: S in regs -> online m/l update -> p' = exp(s - m_run) written to
// atten gmem (unnormalized) + perm-stored to smem -> PV mma with rescaled acc.
// Tail: same-thread re-read of atten p' values (hot in L2), multiply by
// exp(m_chunk - m_final)/l_final, rewrite.
// ---------------------------------------------------------------------------
#define KTS 136   // K^T chunk stride (==8 mod 32)
#define VS  72    // V chunk stride   (==8 mod 32)

__global__ __launch_bounds__(256, 3) void flash_kernel(
    const int* __restrict__ mask, float* __restrict__ atten)
{
    extern __shared__ float sm[];
    float* sQp  = sm;               // 2048: perm Q (8 ks x 2 mi x 128)
    float* sPp  = sQp + 2048;       // 4096: perm P (16 ks x 2 mi x 128)
    float* sBuf = sPp + 4096;       // 9216: K^T chunk (64x136) or V chunk (128x72)
    float* sMk  = sBuf + 9216;      // 1024: mask as float
    float* sM   = sMk + 1024;       // 32: running row max
    float* sL   = sM + 32;          // 32: running row denom
    float* sR   = sL + 32;          // 32: per-chunk rescale
    float* sCM  = sR + 32;          // 256: per-warp chunk max
    float* sCS  = sCM + 256;        // 256: per-warp chunk sum
    float* sKM  = sCS + 256;        // 256: running max snapshot per chunk [8][32]
    // total 17248 floats = 68992 B

    int tile = blockIdx.x, bh = blockIdx.y;
    int b = bh >> 4, h = bh & 15;
    int l0 = tile * 32;
    int tid = threadIdx.x;
    int wid = tid >> 5, lane = tid & 31;
    int g = lane >> 2, t = lane & 3;

    // ---- Stage Q in fragment-permuted order ----
    #pragma unroll
    for (int e = 0; e < 8; e++) {
        int idx = tid + 256 * e;
        int r = idx >> 6, d = idx & 63;
        float q = g_Q[(size_t)(b * LEN + l0 + r) * EMB + h * DH + d];
        int mi = r >> 4, gg = r & 7, jl = (r >> 3) & 1;
        int ksq = d >> 3, tt = d & 3, jh = (d >> 2) & 1;
        sQp[(((ksq << 1) + mi) << 7) + (((gg << 2) | tt) << 2) + (jl + 2 * jh)] =
            __uint_as_float(f2tf(q));
    }
    #pragma unroll
    for (int e = 0; e < 4; e++) {
        int c = tid + 256 * e;
        sMk[c] = (float)mask[b * LEN + c];
    }
    if (tid < 32) { sM[tid] = -3.4e38f; sL[tid] = 0.0f; }
    __syncthreads();

    const unsigned* uQp  = (const unsigned*)sQp;
    const unsigned* uPp  = (const unsigned*)sPp;
    const unsigned* uBuf = (const unsigned*)sBuf;
    const float scale = 0.125f;

    float cv[2][4] = {};

    for (int kt = 0; kt < 8; kt++) {
        int p0 = kt * 128;
        // ---- stage K^T chunk [64 d][128 pos] ----
        #pragma unroll
        for (int e = 0; e < 8; e++) {
            int d = (tid >> 5) + 8 * e, p4 = (tid & 31) * 4;
            float4 v = *(const float4*)&g_KT[((size_t)bh * DH + d) * LEN + p0 + p4];
            *(uint4*)&sBuf[d * KTS + p4] = cvt4(v);
        }
        __syncthreads();

        // ---- QK^T mma ----
        float c[2][2][4] = {};
        #pragma unroll
        for (int ks = 0; ks < 8; ks++) {
            uint4 A0 = *(const uint4*)&uQp[((ks * 2 + 0) << 7) + (lane << 2)];
            uint4 A1 = *(const uint4*)&uQp[((ks * 2 + 1) << 7) + (lane << 2)];
            #pragma unroll
            for (int ni = 0; ni < 2; ni++) {
                int cb = wid * 16 + ni * 8 + g;
                unsigned b0 = uBuf[(ks * 8 + t) * KTS + cb];
                unsigned b1 = uBuf[(ks * 8 + t + 4) * KTS + cb];
                mma8(c[0][ni], A0.x, A0.y, A0.z, A0.w, b0, b1);
                mma8(c[1][ni], A1.x, A1.y, A1.z, A1.w, b0, b1);
            }
        }

        // ---- mask + scale; per-row chunk max ----
        float mx[2][2] = {{-3.4e38f, -3.4e38f}, {-3.4e38f, -3.4e38f}};
        #pragma unroll
        for (int mi = 0; mi < 2; mi++)
            #pragma unroll
            for (int ni = 0; ni < 2; ni++) {
                int colg = p0 + wid * 16 + ni * 8 + 2 * t;
                float k0m = sMk[colg], k1m = sMk[colg + 1];
                float* cc = c[mi][ni];
                cc[0] = (k0m != 0.0f) ? cc[0] * scale : MINV;
                cc[1] = (k1m != 0.0f) ? cc[1] * scale : MINV;
                cc[2] = (k0m != 0.0f) ? cc[2] * scale : MINV;
                cc[3] = (k1m != 0.0f) ? cc[3] * scale : MINV;
                mx[mi][0] = fmaxf(mx[mi][0], fmaxf(cc[0], cc[1]));
                mx[mi][1] = fmaxf(mx[mi][1], fmaxf(cc[2], cc[3]));
            }
        #pragma unroll
        for (int mi = 0; mi < 2; mi++)
            #pragma unroll
            for (int jl = 0; jl < 2; jl++) {
                float v = mx[mi][jl];
                v = fmaxf(v, __shfl_xor_sync(0xffffffffu, v, 1));
                v = fmaxf(v, __shfl_xor_sync(0xffffffffu, v, 2));
                if (t == 0) sCM[wid * 32 + mi * 16 + jl * 8 + g] = v;
            }
        __syncthreads();
        if (tid < 32) {
            float mo = sM[tid], m = mo;
            #pragma unroll
            for (int w = 0; w < 8; w++) m = fmaxf(m, sCM[w * 32 + tid]);
            sR[tid] = fexp(mo - m);
            sM[tid] = m;
            sKM[kt * 32 + tid] = m;
        }
        __syncthreads();

        // ---- p' = exp(s - m_run); atten write; perm store; sums; rescale cv
        float rowm[2][2], rr[2][2];
        #pragma unroll
        for (int mi = 0; mi < 2; mi++)
            #pragma unroll
            for (int jl = 0; jl < 2; jl++) {
                int r = mi * 16 + jl * 8 + g;
                rowm[mi][jl] = sM[r];
                rr[mi][jl]   = sR[r];
            }
        float sums[2][2] = {};
        #pragma unroll
        for (int mi = 0; mi < 2; mi++)
            #pragma unroll
            for (int ni = 0; ni < 2; ni++) {
                int colg = p0 + wid * 16 + ni * 8 + 2 * t;
                float* cc = c[mi][ni];
                float pv0 = fexp(cc[0] - rowm[mi][0]);
                float pv1 = fexp(cc[1] - rowm[mi][0]);
                float pv2 = fexp(cc[2] - rowm[mi][1]);
                float pv3 = fexp(cc[3] - rowm[mi][1]);
                sums[mi][0] += pv0 + pv1;
                sums[mi][1] += pv2 + pv3;
                int row0 = l0 + mi * 16 + g;
                *(float2*)&atten[((size_t)bh * LEN + row0) * LEN + colg] =
                    make_float2(pv0, pv1);
                *(float2*)&atten[((size_t)bh * LEN + row0 + 8) * LEN + colg] =
                    make_float2(pv2, pv3);
                int base = (((wid * 2 + ni) * 2 + mi) << 7);
                int a0a = base + ((g * 4 + 2 * (t & 1)) << 2) + ((t >> 1) << 1);
                sPp[a0a]     = __uint_as_float(f2tf(pv0));
                sPp[a0a + 4] = __uint_as_float(f2tf(pv1));
                sPp[a0a + 1] = __uint_as_float(f2tf(pv2));
                sPp[a0a + 5] = __uint_as_float(f2tf(pv3));
            }
        #pragma unroll
        for (int mi = 0; mi < 2; mi++)
            #pragma unroll
            for (int jl = 0; jl < 2; jl++) {
                float v = sums[mi][jl];
                v += __shfl_xor_sync(0xffffffffu, v, 1);
                v += __shfl_xor_sync(0xffffffffu, v, 2);
                if (t == 0) sCS[wid * 32 + mi * 16 + jl * 8 + g] = v;
            }
        // rescale PV accumulator
        #pragma unroll
        for (int mi = 0; mi < 2; mi++) {
            cv[mi][0] *= rr[mi][0]; cv[mi][1] *= rr[mi][0];
            cv[mi][2] *= rr[mi][1]; cv[mi][3] *= rr[mi][1];
        }
        __syncthreads();
        if (tid < 32) {
            float s = 0.0f;
            #pragma unroll
            for (int w = 0; w < 8; w++) s += sCS[w * 32 + tid];
            sL[tid] = sL[tid] * sR[tid] + s;
        }
        // ---- stage V chunk [128 pos][64 d] (sBuf free after QK mma) ----
        #pragma unroll
        for (int e = 0; e < 8; e++) {
            int p = (tid >> 4) + 16 * e, d4 = (tid & 15) * 4;
            float4 v = *(const float4*)&g_V[(size_t)(b * LEN + p0 + p) * EMB + h * DH + d4];
            *(uint4*)&sBuf[p * VS + d4] = cvt4(v);
        }
        __syncthreads();

        // ---- PV mma ----
        #pragma unroll
        for (int ks = 0; ks < 16; ks++) {
            uint4 A0 = *(const uint4*)&uPp[((ks * 2 + 0) << 7) + (lane << 2)];
            uint4 A1 = *(const uint4*)&uPp[((ks * 2 + 1) << 7) + (lane << 2)];
            unsigned b0 = uBuf[(ks * 8 + t) * VS + wid * 8 + g];
            unsigned b1 = uBuf[(ks * 8 + t + 4) * VS + wid * 8 + g];
            mma8(cv[0], A0.x, A0.y, A0.z, A0.w, b0, b1);
            mma8(cv[1], A1.x, A1.y, A1.z, A1.w, b0, b1);
        }
        __syncthreads();
    }

    // ---- final: normalize O, write g_Val ----
    float li[2][2], mfin[2][2];
    #pragma unroll
    for (int mi = 0; mi < 2; mi++)
        #pragma unroll
        for (int jl = 0; jl < 2; jl++) {
            int r = mi * 16 + jl * 8 + g;
            li[mi][jl]   = 1.0f / sL[r];
            mfin[mi][jl] = sM[r];
        }
    #pragma unroll
    for (int mi = 0; mi < 2; mi++) {
        int row = l0 + mi * 16 + g;
        int col = h * DH + wid * 8 + 2 * t;
        *(float2*)&g_Val[(size_t)(b * LEN + row) * EMB + col] =
            make_float2(cv[mi][0] * li[mi][0], cv[mi][1] * li[mi][0]);
        *(float2*)&g_Val[(size_t)(b * LEN + row + 8) * EMB + col] =
            make_float2(cv[mi][2] * li[mi][1], cv[mi][3] * li[mi][1]);
    }

    // ---- tail: fix up atten (same-thread RAW on identical addresses) ----
    #pragma unroll
    for (int kt = 0; kt < 8; kt++) {
        float fx[2][2];
        #pragma unroll
        for (int mi = 0; mi < 2; mi++)
            #pragma unroll
            for (int jl = 0; jl < 2; jl++) {
                int r = mi * 16 + jl * 8 + g;
                fx[mi][jl] = fexp(sKM[kt * 32 + r] - mfin[mi][jl]) * li[mi][jl];
            }
        #pragma unroll
        for (int mi = 0; mi < 2; mi++)
            #pragma unroll
            for (int ni = 0; ni < 2; ni++) {
                int colg = kt * 128 + wid * 16 + ni * 8 + 2 * t;
                int row0 = l0 + mi * 16 + g;
                float* a0 = &atten[((size_t)bh * LEN + row0) * LEN + colg];
                float* a1 = a0 + 8 * LEN;
                float2 v0 = *(float2*)a0;
                v0.x *= fx[mi][0]; v0.y *= fx[mi][0];
                *(float2*)a0 = v0;
                float2 v1 = *(float2*)a1;
                v1.x *= fx[mi][1]; v1.y *= fx[mi][1];
                *(float2*)a1 = v1;
            }
    }
}

// ---------------------------------------------------------------------------
// Kernel 3: out projection. Block tile 128m x 128n (same layout as qkv).
// Y = Val @ Wo^T + bo + x
// ---------------------------------------------------------------------------
__global__ __launch_bounds__(256) void proj_mma(
    const float* __restrict__ bo, const float* __restrict__ x)
{
    __shared__ unsigned As[128 * AS_STRIDE];
    __shared__ unsigned Bs[32 * BS2];

    int tid = threadIdx.x;
    int wid = tid >> 5, lane = tid & 31;
    int wm = wid & 3, wn = wid >> 2;
    unsigned g = lane >> 2, t = lane & 3;

    int rowbase = blockIdx.y * 128;
    int nbase   = blockIdx.x * 128;

    float acc[2][8][4] = {};

    for (int kb = 0; kb < EMB; kb += 32) {
        #pragma unroll
        for (int e = 0; e < 4; e++) {
            int r  = (tid >> 3) + 32 * e;
            int c4 = (tid & 7) * 4;
            float4 v = *(const float4*)&g_Val[(size_t)(rowbase + r) * EMB + kb + c4];
            *(uint4*)&As[r * AS_STRIDE + c4] = cvt4(v);
        }
        #pragma unroll
        for (int e = 0; e < 4; e++) {
            int idx = tid + 256 * e;
            int k   = idx >> 5;
            int c4  = (idx & 31) * 4;
            float4 v = *(const float4*)&g_WoT[(size_t)(kb + k) * EMB + nbase + c4];
            *(uint4*)&Bs[k * BS2 + c4] = cvt4(v);
        }
        __syncthreads();

        #pragma unroll
        for (int ks = 0; ks < 4; ks++) {
            int k0 = ks * 8;
            unsigned a[2][4];
            #pragma unroll
            for (int mi = 0; mi < 2; mi++) {
                int base = (wm * 32 + mi * 16 + g) * AS_STRIDE + k0 + t;
                a[mi][0] = As[base];
                a[mi][1] = As[base + 8 * AS_STRIDE];
                a[mi][2] = As[base + 4];
                a[mi][3] = As[base + 8 * AS_STRIDE + 4];
            }
            #pragma unroll
            for (int ni = 0; ni < 8; ni++) {
                int cb = wn * 64 + ni * 8 + g;
                unsigned b0 = Bs[(k0 + t) * BS2 + cb];
                unsigned b1 = Bs[(k0 + t + 4) * BS2 + cb];
                mma8(acc[0][ni], a[0][0], a[0][1], a[0][2], a[0][3], b0, b1);
                mma8(acc[1][ni], a[1][0], a[1][1], a[1][2], a[1][3], b0, b1);
            }
        }
        __syncthreads();
    }

    #pragma unroll
    for (int mi = 0; mi < 2; mi++) {
        int row = rowbase + wm * 32 + mi * 16 + g;
        #pragma unroll
        for (int ni = 0; ni < 8; ni++) {
            int col = nbase + wn * 64 + ni * 8 + 2 * t;
            float b0 = bo[col], b1 = bo[col + 1];
            float2 x0 = *(const float2*)&x[(size_t)row * EMB + col];
            float2 x1 = *(const float2*)&x[(size_t)(row + 8) * EMB + col];
            *(float2*)&g_Y[(size_t)row * EMB + col] =
                make_float2(acc[mi][ni][0] + b0 + x0.x, acc[mi][ni][1] + b1 + x0.y);
            *(float2*)&g_Y[(size_t)(row + 8) * EMB + col] =
                make_float2(acc[mi][ni][2] + b0 + x1.x, acc[mi][ni][3] + b1 + x1.y);
        }
    }
}

// ---------------------------------------------------------------------------
// Kernel 4: row LayerNorm (unchanged)
// ---------------------------------------------------------------------------
__global__ __launch_bounds__(256) void ln_kernel(
    const float* __restrict__ gamma, const float* __restrict__ beta,
    float* __restrict__ out)
{
    int r = blockIdx.x;
    const float* row = g_Y + (size_t)r * EMB;
    int tid = threadIdx.x;

    float v[4];
    float s = 0.0f, s2 = 0.0f;
    #pragma unroll
    for (int e = 0; e < 4; e++) {
        v[e] = row[tid + e * 256];
        s  += v[e];
        s2 += v[e] * v[e];
    }
    __shared__ float rs[8], rs2[8];
    #pragma unroll
    for (int o = 16; o; o >>= 1) {
        s  += __shfl_xor_sync(0xffffffffu, s,  o);
        s2 += __shfl_xor_sync(0xffffffffu, s2, o);
    }
    if ((tid & 31) == 0) { rs[tid >> 5] = s; rs2[tid >> 5] = s2; }
    __syncthreads();
    if (tid < 32) {
        float a = (tid < 8) ? rs[tid]  : 0.0f;
        float c = (tid < 8) ? rs2[tid] : 0.0f;
        #pragma unroll
        for (int o = 4; o; o >>= 1) {
            a += __shfl_xor_sync(0xffffffffu, a, o);
            c += __shfl_xor_sync(0xffffffffu, c, o);
        }
        if (tid == 0) { rs[0] = a; rs2[0] = c; }
    }
    __syncthreads();
    float mu  = rs[0] * (1.0f / 1024.0f);
    float var = rs2[0] * (1.0f / 1024.0f) - mu * mu;
    float inv = rsqrtf(var + 1e-5f);
    #pragma unroll
    for (int e = 0; e < 4; e++) {
        int c = tid + e * 256;
        out[(size_t)r * EMB + c] = (v[e] - mu) * inv * gamma[c] + beta[c];
    }
}

// ---------------------------------------------------------------------------
extern "C" void kernel_launch(void* const* d_in, const int* in_sizes, int n_in,
                              void* d_out, int out_size)
{
    const float* x     = (const float*)d_in[0];
    const int*   mask  = (const int*)  d_in[1];
    const float* Wq    = (const float*)d_in[2];
    const float* bq    = (const float*)d_in[3];
    const float* Wk    = (const float*)d_in[4];
    const float* bk    = (const float*)d_in[5];
    const float* Wv    = (const float*)d_in[6];
    const float* bv    = (const float*)d_in[7];
    const float* Wo    = (const float*)d_in[8];
    const float* bo    = (const float*)d_in[9];
    const float* gamma = (const float*)d_in[10];
    const float* beta  = (const float*)d_in[11];

    float* out   = (float*)d_out;                 // [4,1024,1024]
    float* atten = out + (size_t)BL * EMB;        // [4,16,1024,1024]

    const int FLASH_SMEM = 17248 * (int)sizeof(float);
    cudaFuncSetAttribute(flash_kernel,
                         cudaFuncAttributeMaxDynamicSharedMemorySize, FLASH_SMEM);

    transpose_wo<<<dim3(32, 32), dim3(32, 8)>>>(Wo);
    qkv_mma<<<dim3(8, 32, 3), dim3(256)>>>(x, Wq, bq, Wk, bk, Wv, bv);
    transpose_k<<<dim3(32, 2, 64), dim3(32, 8)>>>();
    flash_kernel<<<dim3(32, 64), dim3(256), FLASH_SMEM>>>(mask, atten);
    proj_mma<<<dim3(8, 32), dim3(256)>>>(bo, x);
    ln_kernel<<<BL, 256>>>(gamma, beta, out);
}

// round 6
// speedup vs baseline: 2.6827x; 1.1249x over previous
#include <cuda_runtime.h>
#include <math.h>

#define BLC 4
#define LEN 1024
#define HN 16
#define DH 64
#define EMB 1024
#define BL (BLC*LEN)          // 4096 rows total
#define MINV (-1.7014117e38f) // float32 min / 2

// Scratch (allocation-free rule: __device__ globals)
__device__ float g_Q[BL*EMB];
__device__ float g_K[BL*EMB];
__device__ float g_V[BL*EMB];
__device__ float g_KT[BL*EMB];     // [b*16+h][64 d][1024 pos]
__device__ float g_WoT[EMB*EMB];   // Wo transposed: [k][n]
__device__ float g_Val[BL*EMB];
__device__ float g_Y[BL*EMB];

// ---------------------------------------------------------------------------
// tf32 + fast-exp helpers
// ---------------------------------------------------------------------------
__device__ __forceinline__ unsigned f2tf(float f) {
    unsigned u; asm("cvt.rna.tf32.f32 %0, %1;" : "=r"(u) : "f"(f)); return u;
}
__device__ __forceinline__ uint4 cvt4(float4 v) {
    uint4 u; u.x = f2tf(v.x); u.y = f2tf(v.y); u.z = f2tf(v.z); u.w = f2tf(v.w); return u;
}
__device__ __forceinline__ void mma8(float* c,
                                     unsigned a0, unsigned a1, unsigned a2, unsigned a3,
                                     unsigned b0, unsigned b1) {
    asm volatile(
        "mma.sync.aligned.m16n8k8.row.col.f32.tf32.tf32.f32 "
        "{%0,%1,%2,%3}, {%4,%5,%6,%7}, {%8,%9}, {%0,%1,%2,%3};"
        : "+f"(c[0]), "+f"(c[1]), "+f"(c[2]), "+f"(c[3])
        : "r"(a0), "r"(a1), "r"(a2), "r"(a3), "r"(b0), "r"(b1));
}

// e^x on the FMA pipe (no MUFU). Accurate to ~3e-6 rel. Handles x << 0 -> ~0.
__device__ __forceinline__ float fexp(float x) {
    float y = fmaxf(x * 1.4426950408889634f, -126.0f);
    float tmagic = y + 12582912.0f;          // round-to-nearest-int (|y| < 2^22)
    float r = tmagic - 12582912.0f;
    float f = y - r;                         // f in [-0.5, 0.5]
    int   e = __float_as_int(tmagic);        // low bits = int(y) + 0x4B400000
    float p = 1.33335581e-3f;
    p = fmaf(p, f, 9.61812910e-3f);
    p = fmaf(p, f, 5.55041087e-2f);
    p = fmaf(p, f, 2.40226507e-1f);
    p = fmaf(p, f, 6.93147180e-1f);
    p = fmaf(p, f, 1.0f);
    float s = __int_as_float((e + (127 - 0x4B400000)) << 23);
    return p * s;
}

// ---------------------------------------------------------------------------
// Kernel 1: QKV projections via tf32 mma. Block tile 128m x 128n (2 heads),
// kblock 32. 8 warps: 4(m) x 2(n); warp tile 32x64 = 2 mi x 8 ni frags.
// ---------------------------------------------------------------------------
#define AS_STRIDE 36   // == 4 mod 32
#define BS2 136        // == 8 mod 32

__global__ __launch_bounds__(256) void qkv_mma(
    const float* __restrict__ x,
    const float* __restrict__ Wq, const float* __restrict__ bq,
    const float* __restrict__ Wk, const float* __restrict__ bk,
    const float* __restrict__ Wv, const float* __restrict__ bv)
{
    const float* W; const float* bias; float* out;
    int z = blockIdx.z;
    if (z == 0)      { W = Wq; bias = bq; out = g_Q; }
    else if (z == 1) { W = Wk; bias = bk; out = g_K; }
    else             { W = Wv; bias = bv; out = g_V; }

    __shared__ unsigned As[128 * AS_STRIDE];
    __shared__ unsigned Bs[32 * BS2];

    int tid = threadIdx.x;
    int wid = tid >> 5, lane = tid & 31;
    int wm = wid & 3, wn = wid >> 2;
    unsigned g = lane >> 2, t = lane & 3;

    int rowbase = blockIdx.y * 128;
    int nbase   = blockIdx.x * 128;

    float acc[2][8][4] = {};

    for (int kb = 0; kb < EMB; kb += 32) {
        #pragma unroll
        for (int e = 0; e < 4; e++) {
            int r  = (tid >> 3) + 32 * e;
            int c4 = (tid & 7) * 4;
            float4 v = *(const float4*)&x[(size_t)(rowbase + r) * EMB + kb + c4];
            *(uint4*)&As[r * AS_STRIDE + c4] = cvt4(v);
        }
        #pragma unroll
        for (int e = 0; e < 4; e++) {
            int idx = tid + 256 * e;
            int k   = idx >> 5;
            int c4  = (idx & 31) * 4;
            int head = (nbase + c4) >> 6;
            int hcol = (nbase + c4) & 63;
            float4 v = *(const float4*)&W[(size_t)head * (EMB * DH) + (size_t)(kb + k) * DH + hcol];
            *(uint4*)&Bs[k * BS2 + c4] = cvt4(v);
        }
        __syncthreads();

        #pragma unroll
        for (int ks = 0; ks < 4; ks++) {
            int k0 = ks * 8;
            unsigned a[2][4];
            #pragma unroll
            for (int mi = 0; mi < 2; mi++) {
                int base = (wm * 32 + mi * 16 + g) * AS_STRIDE + k0 + t;
                a[mi][0] = As[base];
                a[mi][1] = As[base + 8 * AS_STRIDE];
                a[mi][2] = As[base + 4];
                a[mi][3] = As[base + 8 * AS_STRIDE + 4];
            }
            #pragma unroll
            for (int ni = 0; ni < 8; ni++) {
                int cb = wn * 64 + ni * 8 + g;
                unsigned b0 = Bs[(k0 + t) * BS2 + cb];
                unsigned b1 = Bs[(k0 + t + 4) * BS2 + cb];
                mma8(acc[0][ni], a[0][0], a[0][1], a[0][2], a[0][3], b0, b1);
                mma8(acc[1][ni], a[1][0], a[1][1], a[1][2], a[1][3], b0, b1);
            }
        }
        __syncthreads();
    }

    #pragma unroll
    for (int mi = 0; mi < 2; mi++) {
        int row = rowbase + wm * 32 + mi * 16 + g;
        #pragma unroll
        for (int ni = 0; ni < 8; ni++) {
            int col = nbase + wn * 64 + ni * 8 + 2 * t;
            float b0 = bias[col], b1 = bias[col + 1];
            *(float2*)&out[(size_t)row * EMB + col] =
                make_float2(acc[mi][ni][0] + b0, acc[mi][ni][1] + b1);
            *(float2*)&out[(size_t)(row + 8) * EMB + col] =
                make_float2(acc[mi][ni][2] + b0, acc[mi][ni][3] + b1);
        }
    }
}

// ---------------------------------------------------------------------------
// Transposes (unchanged)
// ---------------------------------------------------------------------------
__global__ void transpose_k() {
    __shared__ float tl[32][33];
    int bh = blockIdx.z;
    int b = bh >> 4, h = bh & 15;
    int p0 = blockIdx.x * 32, d0 = blockIdx.y * 32;
    int tx = threadIdx.x, ty = threadIdx.y;
    #pragma unroll
    for (int j = 0; j < 4; j++)
        tl[ty + 8 * j][tx] =
            g_K[(size_t)(b * LEN + p0 + ty + 8 * j) * EMB + h * DH + d0 + tx];
    __syncthreads();
    #pragma unroll
    for (int j = 0; j < 4; j++)
        g_KT[((size_t)bh * DH + d0 + ty + 8 * j) * LEN + p0 + tx] = tl[tx][ty + 8 * j];
}

__global__ void transpose_wo(const float* __restrict__ Wo) {
    __shared__ float tl[32][33];
    int n0 = blockIdx.y * 32, k0 = blockIdx.x * 32;
    int tx = threadIdx.x, ty = threadIdx.y;
    #pragma unroll
    for (int j = 0; j < 4; j++)
        tl[ty + 8 * j][tx] = Wo[(size_t)(n0 + ty + 8 * j) * EMB + k0 + tx];
    __syncthreads();
    #pragma unroll
    for (int j = 0; j < 4; j++)
        g_WoT[(size_t)(k0 + ty + 8 * j) * EMB + n0 + tx] = tl[tx][ty + 8 * j];
}

// ---------------------------------------------------------------------------
// Kernel 2: ONE-PASS flash attention, 64 q-rows / CTA, 512 threads,
// 16 warps as 4(m-groups of 16 rows) x 4(n-groups of 32 cols).
// Per chunk (128 key positions): QK mma -> online m/l -> p' = exp(s-m_run)
// -> atten gmem (unnormalized) + perm smem -> PV mma with rescaled acc.
// Tail: same-thread atten fixup with exp(m_chunk - m_final)/l_final.
// ---------------------------------------------------------------------------
#define KTS 136   // K^T chunk stride (==8 mod 32)
#define VS  72    // V chunk stride   (==8 mod 32)
#define FROWS 64

__global__ __launch_bounds__(512, 2) void flash_kernel(
    const int* __restrict__ mask, float* __restrict__ atten)
{
    extern __shared__ float sm[];
    float* sQp  = sm;               // 4096: perm Q (8 ks x 4 wm x 128)
    float* sPp  = sQp + 4096;       // 8192: perm P (16 ks x 4 wm x 128)
    float* sBuf = sPp + 8192;       // 9216: K^T chunk (64x136) or V chunk (128x72)
    float* sMk  = sBuf + 9216;      // 1024: mask as float
    float* sM   = sMk + 1024;       // 64: running row max
    float* sL   = sM + 64;          // 64: running row denom
    float* sR   = sL + 64;          // 64: per-chunk rescale
    float* sCM  = sR + 64;          // 256: per n-group chunk max [4][64]
    float* sCS  = sCM + 256;        // 256: per n-group chunk sum [4][64]
    float* sKM  = sCS + 256;        // 512: running max snapshot per chunk [8][64]
    // total 23744 floats = 94976 B

    int tile = blockIdx.x, bh = blockIdx.y;
    int b = bh >> 4, h = bh & 15;
    int l0 = tile * FROWS;
    int tid = threadIdx.x;
    int wid = tid >> 5, lane = tid & 31;
    int wm = wid & 3, wn = wid >> 2;
    int g = lane >> 2, t = lane & 3;

    // ---- Stage Q [64 x 64] in fragment-permuted order ----
    #pragma unroll
    for (int e = 0; e < 8; e++) {
        int idx = tid + 512 * e;
        int r = idx >> 6, d = idx & 63;
        float q = g_Q[(size_t)(b * LEN + l0 + r) * EMB + h * DH + d];
        int wmq = r >> 4, gg = r & 7, jl = (r >> 3) & 1;
        int ksq = d >> 3, tt = d & 3, jh = (d >> 2) & 1;
        sQp[(((ksq << 2) + wmq) << 7) + (((gg << 2) | tt) << 2) + (jl + 2 * jh)] =
            __uint_as_float(f2tf(q));
    }
    #pragma unroll
    for (int e = 0; e < 2; e++) {
        int c = tid + 512 * e;
        sMk[c] = (float)mask[b * LEN + c];
    }
    if (tid < FROWS) { sM[tid] = -3.4e38f; sL[tid] = 0.0f; }
    __syncthreads();

    const unsigned* uQp  = (const unsigned*)sQp;
    const unsigned* uPp  = (const unsigned*)sPp;
    const unsigned* uBuf = (const unsigned*)sBuf;
    const float scale = 0.125f;

    float cv[2][4] = {};

    for (int kt = 0; kt < 8; kt++) {
        int p0 = kt * 128;
        // ---- stage K^T chunk [64 d][128 pos] ----
        #pragma unroll
        for (int e = 0; e < 4; e++) {
            int d = (tid >> 5) + 16 * e, p4 = (tid & 31) * 4;
            float4 v = *(const float4*)&g_KT[((size_t)bh * DH + d) * LEN + p0 + p4];
            *(uint4*)&sBuf[d * KTS + p4] = cvt4(v);
        }
        __syncthreads();

        // ---- QK^T mma: warp tile 16 rows x 32 cols ----
        float c[4][4] = {};
        #pragma unroll
        for (int ks = 0; ks < 8; ks++) {
            uint4 A = *(const uint4*)&uQp[(((ks << 2) + wm) << 7) + (lane << 2)];
            #pragma unroll
            for (int ni = 0; ni < 4; ni++) {
                int cb = wn * 32 + ni * 8 + g;
                unsigned b0 = uBuf[(ks * 8 + t) * KTS + cb];
                unsigned b1 = uBuf[(ks * 8 + t + 4) * KTS + cb];
                mma8(c[ni], A.x, A.y, A.z, A.w, b0, b1);
            }
        }

        // ---- mask + scale; per-row chunk max ----
        float mx[2] = {-3.4e38f, -3.4e38f};
        #pragma unroll
        for (int ni = 0; ni < 4; ni++) {
            int colg = p0 + wn * 32 + ni * 8 + 2 * t;
            float k0m = sMk[colg], k1m = sMk[colg + 1];
            float* cc = c[ni];
            cc[0] = (k0m != 0.0f) ? cc[0] * scale : MINV;
            cc[1] = (k1m != 0.0f) ? cc[1] * scale : MINV;
            cc[2] = (k0m != 0.0f) ? cc[2] * scale : MINV;
            cc[3] = (k1m != 0.0f) ? cc[3] * scale : MINV;
            mx[0] = fmaxf(mx[0], fmaxf(cc[0], cc[1]));
            mx[1] = fmaxf(mx[1], fmaxf(cc[2], cc[3]));
        }
        #pragma unroll
        for (int jl = 0; jl < 2; jl++) {
            float v = mx[jl];
            v = fmaxf(v, __shfl_xor_sync(0xffffffffu, v, 1));
            v = fmaxf(v, __shfl_xor_sync(0xffffffffu, v, 2));
            if (t == 0) sCM[wn * 64 + wm * 16 + jl * 8 + g] = v;
        }
        __syncthreads();
        if (tid < FROWS) {
            float mo = sM[tid], m = mo;
            #pragma unroll
            for (int w = 0; w < 4; w++) m = fmaxf(m, sCM[w * 64 + tid]);
            sR[tid] = fexp(mo - m);
            sM[tid] = m;
            sKM[kt * 64 + tid] = m;
        }
        __syncthreads();

        // ---- p' = exp(s - m_run); atten write; perm store; sums ----
        float rowm[2], rr[2];
        #pragma unroll
        for (int jl = 0; jl < 2; jl++) {
            int r = wm * 16 + jl * 8 + g;
            rowm[jl] = sM[r];
            rr[jl]   = sR[r];
        }
        float sums[2] = {};
        #pragma unroll
        for (int ni = 0; ni < 4; ni++) {
            int colg = p0 + wn * 32 + ni * 8 + 2 * t;
            float* cc = c[ni];
            float pv0 = fexp(cc[0] - rowm[0]);
            float pv1 = fexp(cc[1] - rowm[0]);
            float pv2 = fexp(cc[2] - rowm[1]);
            float pv3 = fexp(cc[3] - rowm[1]);
            sums[0] += pv0 + pv1;
            sums[1] += pv2 + pv3;
            int row0 = l0 + wm * 16 + g;
            *(float2*)&atten[((size_t)bh * LEN + row0) * LEN + colg] =
                make_float2(pv0, pv1);
            *(float2*)&atten[((size_t)bh * LEN + row0 + 8) * LEN + colg] =
                make_float2(pv2, pv3);
            int ksP = wn * 4 + ni;
            int a0a = (((ksP << 2) + wm) << 7) +
                      ((g * 4 + 2 * (t & 1)) << 2) + ((t >> 1) << 1);
            sPp[a0a]     = __uint_as_float(f2tf(pv0));
            sPp[a0a + 4] = __uint_as_float(f2tf(pv1));
            sPp[a0a + 1] = __uint_as_float(f2tf(pv2));
            sPp[a0a + 5] = __uint_as_float(f2tf(pv3));
        }
        #pragma unroll
        for (int jl = 0; jl < 2; jl++) {
            float v = sums[jl];
            v += __shfl_xor_sync(0xffffffffu, v, 1);
            v += __shfl_xor_sync(0xffffffffu, v, 2);
            if (t == 0) sCS[wn * 64 + wm * 16 + jl * 8 + g] = v;
        }
        // rescale PV accumulator
        cv[0][0] *= rr[0]; cv[0][1] *= rr[0];
        cv[0][2] *= rr[1]; cv[0][3] *= rr[1];
        cv[1][0] *= rr[0]; cv[1][1] *= rr[0];
        cv[1][2] *= rr[1]; cv[1][3] *= rr[1];

        // ---- stage V chunk [128 pos][64 d] (K^T dead after QK mma) ----
        #pragma unroll
        for (int e = 0; e < 4; e++) {
            int p = (tid >> 4) + 32 * e, d4 = (tid & 15) * 4;
            float4 v = *(const float4*)&g_V[(size_t)(b * LEN + p0 + p) * EMB + h * DH + d4];
            *(uint4*)&sBuf[p * VS + d4] = cvt4(v);
        }
        __syncthreads();

        if (tid < FROWS) {
            float s = 0.0f;
            #pragma unroll
            for (int w = 0; w < 4; w++) s += sCS[w * 64 + tid];
            sL[tid] = sL[tid] * sR[tid] + s;
        }

        // ---- PV mma: warp tile 16 rows x 16 d ----
        #pragma unroll
        for (int ks = 0; ks < 16; ks++) {
            uint4 A = *(const uint4*)&uPp[(((ks << 2) + wm) << 7) + (lane << 2)];
            #pragma unroll
            for (int ni = 0; ni < 2; ni++) {
                int cb = wn * 16 + ni * 8 + g;
                unsigned b0 = uBuf[(ks * 8 + t) * VS + cb];
                unsigned b1 = uBuf[(ks * 8 + t + 4) * VS + cb];
                mma8(cv[ni], A.x, A.y, A.z, A.w, b0, b1);
            }
        }
        __syncthreads();
    }

    // ---- final: normalize O, write g_Val ----
    float li[2], mfin[2];
    #pragma unroll
    for (int jl = 0; jl < 2; jl++) {
        int r = wm * 16 + jl * 8 + g;
        li[jl]   = 1.0f / sL[r];
        mfin[jl] = sM[r];
    }
    #pragma unroll
    for (int ni = 0; ni < 2; ni++) {
        int row = l0 + wm * 16 + g;
        int col = h * DH + wn * 16 + ni * 8 + 2 * t;
        *(float2*)&g_Val[(size_t)(b * LEN + row) * EMB + col] =
            make_float2(cv[ni][0] * li[0], cv[ni][1] * li[0]);
        *(float2*)&g_Val[(size_t)(b * LEN + row + 8) * EMB + col] =
            make_float2(cv[ni][2] * li[1], cv[ni][3] * li[1]);
    }

    // ---- tail: fix up atten (same-thread RAW on identical addresses) ----
    #pragma unroll
    for (int kt = 0; kt < 8; kt++) {
        float fx[2];
        #pragma unroll
        for (int jl = 0; jl < 2; jl++) {
            int r = wm * 16 + jl * 8 + g;
            fx[jl] = fexp(sKM[kt * 64 + r] - mfin[jl]) * li[jl];
        }
        #pragma unroll
        for (int ni = 0; ni < 4; ni++) {
            int colg = kt * 128 + wn * 32 + ni * 8 + 2 * t;
            int row0 = l0 + wm * 16 + g;
            float* a0 = &atten[((size_t)bh * LEN + row0) * LEN + colg];
            float* a1 = a0 + 8 * LEN;
            float2 v0 = *(float2*)a0;
            v0.x *= fx[0]; v0.y *= fx[0];
            *(float2*)a0 = v0;
            float2 v1 = *(float2*)a1;
            v1.x *= fx[1]; v1.y *= fx[1];
            *(float2*)a1 = v1;
        }
    }
}

// ---------------------------------------------------------------------------
// Kernel 3: out projection. Block tile 128m x 128n. Y = Val @ Wo^T + bo + x
// ---------------------------------------------------------------------------
__global__ __launch_bounds__(256) void proj_mma(
    const float* __restrict__ bo, const float* __restrict__ x)
{
    __shared__ unsigned As[128 * AS_STRIDE];
    __shared__ unsigned Bs[32 * BS2];

    int tid = threadIdx.x;
    int wid = tid >> 5, lane = tid & 31;
    int wm = wid & 3, wn = wid >> 2;
    unsigned g = lane >> 2, t = lane & 3;

    int rowbase = blockIdx.y * 128;
    int nbase   = blockIdx.x * 128;

    float acc[2][8][4] = {};

    for (int kb = 0; kb < EMB; kb += 32) {
        #pragma unroll
        for (int e = 0; e < 4; e++) {
            int r  = (tid >> 3) + 32 * e;
            int c4 = (tid & 7) * 4;
            float4 v = *(const float4*)&g_Val[(size_t)(rowbase + r) * EMB + kb + c4];
            *(uint4*)&As[r * AS_STRIDE + c4] = cvt4(v);
        }
        #pragma unroll
        for (int e = 0; e < 4; e++) {
            int idx = tid + 256 * e;
            int k   = idx >> 5;
            int c4  = (idx & 31) * 4;
            float4 v = *(const float4*)&g_WoT[(size_t)(kb + k) * EMB + nbase + c4];
            *(uint4*)&Bs[k * BS2 + c4] = cvt4(v);
        }
        __syncthreads();

        #pragma unroll
        for (int ks = 0; ks < 4; ks++) {
            int k0 = ks * 8;
            unsigned a[2][4];
            #pragma unroll
            for (int mi = 0; mi < 2; mi++) {
                int base = (wm * 32 + mi * 16 + g) * AS_STRIDE + k0 + t;
                a[mi][0] = As[base];
                a[mi][1] = As[base + 8 * AS_STRIDE];
                a[mi][2] = As[base + 4];
                a[mi][3] = As[base + 8 * AS_STRIDE + 4];
            }
            #pragma unroll
            for (int ni = 0; ni < 8; ni++) {
                int cb = wn * 64 + ni * 8 + g;
                unsigned b0 = Bs[(k0 + t) * BS2 + cb];
                unsigned b1 = Bs[(k0 + t + 4) * BS2 + cb];
                mma8(acc[0][ni], a[0][0], a[0][1], a[0][2], a[0][3], b0, b1);
                mma8(acc[1][ni], a[1][0], a[1][1], a[1][2], a[1][3], b0, b1);
            }
        }
        __syncthreads();
    }

    #pragma unroll
    for (int mi = 0; mi < 2; mi++) {
        int row = rowbase + wm * 32 + mi * 16 + g;
        #pragma unroll
        for (int ni = 0; ni < 8; ni++) {
            int col = nbase + wn * 64 + ni * 8 + 2 * t;
            float b0 = bo[col], b1 = bo[col + 1];
            float2 x0 = *(const float2*)&x[(size_t)row * EMB + col];
            float2 x1 = *(const float2*)&x[(size_t)(row + 8) * EMB + col];
            *(float2*)&g_Y[(size_t)row * EMB + col] =
                make_float2(acc[mi][ni][0] + b0 + x0.x, acc[mi][ni][1] + b1 + x0.y);
            *(float2*)&g_Y[(size_t)(row + 8) * EMB + col] =
                make_float2(acc[mi][ni][2] + b0 + x1.x, acc[mi][ni][3] + b1 + x1.y);
        }
    }
}

// ---------------------------------------------------------------------------
// Kernel 4: row LayerNorm (unchanged)
// ---------------------------------------------------------------------------
__global__ __launch_bounds__(256) void ln_kernel(
    const float* __restrict__ gamma, const float* __restrict__ beta,
    float* __restrict__ out)
{
    int r = blockIdx.x;
    const float* row = g_Y + (size_t)r * EMB;
    int tid = threadIdx.x;

    float v[4];
    float s = 0.0f, s2 = 0.0f;
    #pragma unroll
    for (int e = 0; e < 4; e++) {
        v[e] = row[tid + e * 256];
        s  += v[e];
        s2 += v[e] * v[e];
    }
    __shared__ float rs[8], rs2[8];
    #pragma unroll
    for (int o = 16; o; o >>= 1) {
        s  += __shfl_xor_sync(0xffffffffu, s,  o);
        s2 += __shfl_xor_sync(0xffffffffu, s2, o);
    }
    if ((tid & 31) == 0) { rs[tid >> 5] = s; rs2[tid >> 5] = s2; }
    __syncthreads();
    if (tid < 32) {
        float a = (tid < 8) ? rs[tid]  : 0.0f;
        float c = (tid < 8) ? rs2[tid] : 0.0f;
        #pragma unroll
        for (int o = 4; o; o >>= 1) {
            a += __shfl_xor_sync(0xffffffffu, a, o);
            c += __shfl_xor_sync(0xffffffffu, c, o);
        }
        if (tid == 0) { rs[0] = a; rs2[0] = c; }
    }
    __syncthreads();
    float mu  = rs[0] * (1.0f / 1024.0f);
    float var = rs2[0] * (1.0f / 1024.0f) - mu * mu;
    float inv = rsqrtf(var + 1e-5f);
    #pragma unroll
    for (int e = 0; e < 4; e++) {
        int c = tid + e * 256;
        out[(size_t)r * EMB + c] = (v[e] - mu) * inv * gamma[c] + beta[c];
    }
}

// ---------------------------------------------------------------------------
extern "C" void kernel_launch(void* const* d_in, const int* in_sizes, int n_in,
                              void* d_out, int out_size)
{
    const float* x     = (const float*)d_in[0];
    const int*   mask  = (const int*)  d_in[1];
    const float* Wq    = (const float*)d_in[2];
    const float* bq    = (const float*)d_in[3];
    const float* Wk    = (const float*)d_in[4];
    const float* bk    = (const float*)d_in[5];
    const float* Wv    = (const float*)d_in[6];
    const float* bv    = (const float*)d_in[7];
    const float* Wo    = (const float*)d_in[8];
    const float* bo    = (const float*)d_in[9];
    const float* gamma = (const float*)d_in[10];
    const float* beta  = (const float*)d_in[11];

    float* out   = (float*)d_out;                 // [4,1024,1024]
    float* atten = out + (size_t)BL * EMB;        // [4,16,1024,1024]

    const int FLASH_SMEM = 23744 * (int)sizeof(float);
    cudaFuncSetAttribute(flash_kernel,
                         cudaFuncAttributeMaxDynamicSharedMemorySize, FLASH_SMEM);

    transpose_wo<<<dim3(32, 32), dim3(32, 8)>>>(Wo);
    qkv_mma<<<dim3(8, 32, 3), dim3(256)>>>(x, Wq, bq, Wk, bk, Wv, bv);
    transpose_k<<<dim3(32, 2, 64), dim3(32, 8)>>>();
    flash_kernel<<<dim3(16, 64), dim3(512), FLASH_SMEM>>>(mask, atten);
    proj_mma<<<dim3(8, 32), dim3(256)>>>(bo, x);
    ln_kernel<<<BL, 256>>>(gamma, beta, out);
}